// round 10
// baseline (speedup 1.0000x reference)
#include <cuda_runtime.h>
#include <cstdint>

// Problem constants
#define BSZ     4
#define SEQ     2048
#define DIMSZ   512
#define HEADS   8
#define HD      64
#define M_TOT   (BSZ * SEQ)   // 8192
#define NEGV    (-1000000.0f)

// Scratch (device globals: allocation rules forbid cudaMalloc)
__device__ float g_Q[M_TOT * DIMSZ];
__device__ float g_K[M_TOT * DIMSZ];
__device__ float g_V[M_TOT * DIMSZ];
__device__ float g_A[M_TOT * DIMSZ];

// ===========================================================================
// Helpers: compute_103-safe PTX only (mma.sync / ldmatrix / cvt.rna.tf32)
// ===========================================================================
__device__ __forceinline__ uint32_t smem_u32(const void* p) {
    uint32_t a;
    asm("{ .reg .u64 t; cvta.to.shared.u64 t, %1; cvt.u32.u64 %0, t; }"
        : "=r"(a) : "l"(p));
    return a;
}

__device__ __forceinline__ uint32_t f2tf(float f) {
    uint32_t u;
    asm("cvt.rna.tf32.f32 %0, %1;" : "=r"(u) : "f"(f));
    return u;
}

__device__ __forceinline__ uint4 cvt4(float4 v) {
    uint4 t;
    t.x = f2tf(v.x); t.y = f2tf(v.y); t.z = f2tf(v.z); t.w = f2tf(v.w);
    return t;
}

__device__ __forceinline__ void ldsm4(uint32_t& r0, uint32_t& r1,
                                      uint32_t& r2, uint32_t& r3,
                                      uint32_t addr) {
    asm volatile("ldmatrix.sync.aligned.m8n8.x4.shared.b16 {%0,%1,%2,%3}, [%4];"
                 : "=r"(r0), "=r"(r1), "=r"(r2), "=r"(r3) : "r"(addr));
}

// D (fp32) += A(tf32 row-major m16 x k8) * B(tf32 col-major k8 x n8)
__device__ __forceinline__ void mma_tf32(float* d, const uint32_t* a,
                                         uint32_t b0, uint32_t b1) {
    asm volatile(
        "mma.sync.aligned.m16n8k8.row.col.f32.tf32.tf32.f32 "
        "{%0,%1,%2,%3}, {%4,%5,%6,%7}, {%8,%9}, {%0,%1,%2,%3};"
        : "+f"(d[0]), "+f"(d[1]), "+f"(d[2]), "+f"(d[3])
        : "r"(a[0]), "r"(a[1]), "r"(a[2]), "r"(a[3]), "r"(b0), "r"(b1));
}

// ===========================================================================
// GEMM:  D[M,512] = A[M,512] * W[512,512]^T   (tf32 mma, fp32 acc)
// CTA tile 128(m) x 64(n), 256 threads, warp tile 32x32, K-chunks of 32.
// SMEM rows = 32 floats (128B, 8 x 16B chunks), xor-swizzled, double-buffered.
// ===========================================================================
#define G_STAGE 24576      // A tile 16KB + W tile 8KB
#define G_SMEM  (2 * G_STAGE)

__global__ __launch_bounds__(256, 2)
void gemm_tc(const float* __restrict__ A, const float* __restrict__ W,
             float* __restrict__ D)
{
    extern __shared__ char sm[];
    const uint32_t sb = smem_u32(sm);
    const int tid = threadIdx.x;
    const int l   = tid & 31;
    const int wid = tid >> 5;
    const int wm  = wid & 3;        // 4 warps along M
    const int wn  = wid >> 2;       // 2 warps along N
    const int rowBase = blockIdx.y * 128;
    const int colBase = blockIdx.x * 64;

    float4 pa[4], pw[2];

    // prefetch chunk c into regs
    auto prefetch = [&](int c) {
#pragma unroll
        for (int i = 0; i < 4; i++) {
            int idx = tid + i * 256;           // 0..1023
            int r = idx >> 3, cc = idx & 7;
            pa[i] = *(const float4*)&A[(size_t)(rowBase + r) * DIMSZ + c * 32 + cc * 4];
        }
#pragma unroll
        for (int i = 0; i < 2; i++) {
            int idx = tid + i * 256;           // 0..511
            int r = idx >> 3, cc = idx & 7;
            pw[i] = *(const float4*)&W[(size_t)(colBase + r) * DIMSZ + c * 32 + cc * 4];
        }
    };
    // store regs into buffer (tf32-converted, swizzled)
    auto stage = [&](int buf) {
        char* base = sm + buf * G_STAGE;
#pragma unroll
        for (int i = 0; i < 4; i++) {
            int idx = tid + i * 256;
            int r = idx >> 3, cc = idx & 7;
            *(uint4*)(base + r * 128 + ((cc ^ (r & 7)) << 4)) = cvt4(pa[i]);
        }
#pragma unroll
        for (int i = 0; i < 2; i++) {
            int idx = tid + i * 256;
            int r = idx >> 3, cc = idx & 7;
            *(uint4*)(base + 16384 + r * 128 + ((cc ^ (r & 7)) << 4)) = cvt4(pw[i]);
        }
    };

    float acc[2][4][4];
#pragma unroll
    for (int im = 0; im < 2; im++)
#pragma unroll
        for (int j = 0; j < 4; j++)
#pragma unroll
            for (int q = 0; q < 4; q++) acc[im][j][q] = 0.f;

    prefetch(0);
    stage(0);

    for (int c = 0; c < 16; ++c) {
        __syncthreads();
        if (c < 15) prefetch(c + 1);
        const uint32_t abase = sb + (c & 1) * G_STAGE;
        const uint32_t wbase = abase + 16384;
#pragma unroll
        for (int s = 0; s < 4; ++s) {
            uint32_t a[2][4];
#pragma unroll
            for (int im = 0; im < 2; im++) {
                int r = 32 * wm + 16 * im + (l & 7) + (((l >> 3) & 1) << 3);
                int cc = (2 * s + (l >> 4)) ^ (r & 7);
                ldsm4(a[im][0], a[im][1], a[im][2], a[im][3],
                      abase + r * 128 + (cc << 4));
            }
            uint32_t b[4][2];
#pragma unroll
            for (int p = 0; p < 2; p++) {
                int r = 32 * wn + 16 * p + (l & 7) + ((l >> 4) << 3);
                int cc = (2 * s + ((l >> 3) & 1)) ^ (r & 7);
                ldsm4(b[2 * p][0], b[2 * p][1], b[2 * p + 1][0], b[2 * p + 1][1],
                      wbase + r * 128 + (cc << 4));
            }
#pragma unroll
            for (int im = 0; im < 2; im++)
#pragma unroll
                for (int j = 0; j < 4; j++)
                    mma_tf32(acc[im][j], a[im], b[j][0], b[j][1]);
        }
        if (c < 15) stage((c + 1) & 1);
    }

    // epilogue
#pragma unroll
    for (int im = 0; im < 2; im++) {
        int r0 = rowBase + 32 * wm + 16 * im + (l >> 2);
#pragma unroll
        for (int j = 0; j < 4; j++) {
            int col = colBase + 32 * wn + 8 * j + 2 * (l & 3);
            *(float2*)&D[(size_t)r0 * DIMSZ + col] =
                make_float2(acc[im][j][0], acc[im][j][1]);
            *(float2*)&D[(size_t)(r0 + 8) * DIMSZ + col] =
                make_float2(acc[im][j][2], acc[im][j][3]);
        }
    }
}

// ===========================================================================
// Fused flash-attention with tf32 mma.sync.
// CTA: 128 q-rows of one (b,h); 8 warps; warp owns 16 q-rows.
// KV tiles of 64.  SMEM rows = 64 floats (256B, 16 chunks), xor-swizzled.
//   Qs[128][64]  (q, d)    pre-scaled by 1/8, tf32
//   Ks[64][64]   (key, d)  tf32
//   Vt[64][64]   (d, key)  tf32 (transposed during staging)
//   Ps[128][64]  (q, key)  tf32
// ===========================================================================
#define AT_QS   0
#define AT_KS   32768
#define AT_VT   49152
#define AT_PS   65536
#define AT_MSK  98304
#define AT_SMEM (98304 + 256)

__global__ __launch_bounds__(256, 2)
void attn_tc(const float* __restrict__ Q, const float* __restrict__ K,
             const float* __restrict__ V, const int* __restrict__ mask,
             float* __restrict__ Aout)
{
    extern __shared__ char sm[];
    const uint32_t sb = smem_u32(sm);
    int* msk = (int*)(sm + AT_MSK);

    const int tid = threadIdx.x;
    const int l   = tid & 31;
    const int w   = tid >> 5;       // warp id: rows 16*w
    const int b   = blockIdx.z;
    const int h   = blockIdx.y;
    const int qb  = blockIdx.x * 128;

    const float* Qb = Q + ((size_t)b * SEQ) * DIMSZ + h * HD;
    const float* Kb = K + ((size_t)b * SEQ) * DIMSZ + h * HD;
    const float* Vb = V + ((size_t)b * SEQ) * DIMSZ + h * HD;
    const int*   mb = mask + b * SEQ;

    // Load Q tile once: (q,d), scaled 1/8, tf32, swizzled
#pragma unroll
    for (int i = 0; i < 8; i++) {
        int idx = tid + i * 256;      // 0..2047
        int r = idx >> 4, cc = idx & 15;
        float4 v = *(const float4*)&Qb[(size_t)(qb + r) * DIMSZ + cc * 4];
        v.x *= 0.125f; v.y *= 0.125f; v.z *= 0.125f; v.w *= 0.125f;
        *(uint4*)(sm + AT_QS + r * 256 + ((cc ^ (r & 7)) << 4)) = cvt4(v);
    }

    float O[8][4];
    float m0 = -1e30f, m1 = -1e30f, l0 = 0.f, l1 = 0.f;
#pragma unroll
    for (int j = 0; j < 8; j++)
#pragma unroll
        for (int q = 0; q < 4; q++) O[j][q] = 0.f;

    for (int k0 = 0; k0 < SEQ; k0 += 64) {
        __syncthreads();   // prev tile's PV reads of Ks/Vt complete
        // stage K (natural) and V (transposed)
#pragma unroll
        for (int i = 0; i < 4; i++) {
            int idx = tid + i * 256;   // 0..1023
            int key = idx >> 4, cc = idx & 15;
            float4 kv = *(const float4*)&Kb[(size_t)(k0 + key) * DIMSZ + cc * 4];
            *(uint4*)(sm + AT_KS + key * 256 + ((cc ^ (key & 7)) << 4)) = cvt4(kv);
            float4 vv = *(const float4*)&Vb[(size_t)(k0 + key) * DIMSZ + cc * 4];
            int d0 = cc * 4;
            int kc = key >> 2, ko = (key & 3) * 4;
            *(uint32_t*)(sm + AT_VT + (d0+0) * 256 + ((kc ^ ((d0+0) & 7)) << 4) + ko) = f2tf(vv.x);
            *(uint32_t*)(sm + AT_VT + (d0+1) * 256 + ((kc ^ ((d0+1) & 7)) << 4) + ko) = f2tf(vv.y);
            *(uint32_t*)(sm + AT_VT + (d0+2) * 256 + ((kc ^ ((d0+2) & 7)) << 4) + ko) = f2tf(vv.z);
            *(uint32_t*)(sm + AT_VT + (d0+3) * 256 + ((kc ^ ((d0+3) & 7)) << 4) + ko) = f2tf(vv.w);
        }
        if (tid < 64) msk[tid] = mb[k0 + tid];
        __syncthreads();

        // ---- S = Qs * Ks^T : warp rows 16w, 8 key-atoms, 8 d-steps ----
        float S[8][4];
#pragma unroll
        for (int j = 0; j < 8; j++)
#pragma unroll
            for (int q = 0; q < 4; q++) S[j][q] = 0.f;

#pragma unroll
        for (int s = 0; s < 8; ++s) {
            uint32_t a[4];
            {
                int r = 16 * w + (l & 7) + (((l >> 3) & 1) << 3);
                int cc = (2 * s + (l >> 4)) ^ (r & 7);
                ldsm4(a[0], a[1], a[2], a[3], sb + AT_QS + r * 256 + (cc << 4));
            }
            uint32_t bq[8][2];
#pragma unroll
            for (int p = 0; p < 4; p++) {
                int r = 16 * p + (l & 7) + ((l >> 4) << 3);
                int cc = (2 * s + ((l >> 3) & 1)) ^ (r & 7);
                ldsm4(bq[2*p][0], bq[2*p][1], bq[2*p+1][0], bq[2*p+1][1],
                      sb + AT_KS + r * 256 + (cc << 4));
            }
#pragma unroll
            for (int j = 0; j < 8; j++)
                mma_tf32(S[j], a, bq[j][0], bq[j][1]);
        }

        // ---- mask (Q pre-scaled, so S already /8) ----
#pragma unroll
        for (int j = 0; j < 8; j++) {
            int kA = 8 * j + 2 * (l & 3);
            int mA = msk[kA], mB = msk[kA + 1];
            S[j][0] = mA ? S[j][0] : NEGV;
            S[j][1] = mB ? S[j][1] : NEGV;
            S[j][2] = mA ? S[j][2] : NEGV;
            S[j][3] = mB ? S[j][3] : NEGV;
        }

        // ---- online softmax (rows l/4 and l/4+8; quad = lanes sharing l/4) ----
        float mx0 = -1e30f, mx1 = -1e30f;
#pragma unroll
        for (int j = 0; j < 8; j++) {
            mx0 = fmaxf(mx0, fmaxf(S[j][0], S[j][1]));
            mx1 = fmaxf(mx1, fmaxf(S[j][2], S[j][3]));
        }
        mx0 = fmaxf(mx0, __shfl_xor_sync(0xffffffffu, mx0, 1));
        mx0 = fmaxf(mx0, __shfl_xor_sync(0xffffffffu, mx0, 2));
        mx1 = fmaxf(mx1, __shfl_xor_sync(0xffffffffu, mx1, 1));
        mx1 = fmaxf(mx1, __shfl_xor_sync(0xffffffffu, mx1, 2));

        float mn0 = fmaxf(m0, mx0), mn1 = fmaxf(m1, mx1);
        float cr0 = __expf(m0 - mn0), cr1 = __expf(m1 - mn1);
        m0 = mn0; m1 = mn1;

        float rs0 = 0.f, rs1 = 0.f;
        const int qr  = 16 * w + (l >> 2);
        const int kAc = 2 * (l & 3);          // key offset within atom
#pragma unroll
        for (int j = 0; j < 8; j++) {
            float p0 = __expf(S[j][0] - mn0);
            float p1 = __expf(S[j][1] - mn0);
            float p2 = __expf(S[j][2] - mn1);
            float p3 = __expf(S[j][3] - mn1);
            rs0 += p0 + p1; rs1 += p2 + p3;
            // store P (tf32) to Ps[q][key]
            int kA = 8 * j + kAc;
            int kc = kA >> 2, ko = (kA & 3) * 4;
            *(uint2*)(sm + AT_PS + qr * 256 + ((kc ^ (qr & 7)) << 4) + ko) =
                make_uint2(f2tf(p0), f2tf(p1));
            int qr8 = qr + 8;
            *(uint2*)(sm + AT_PS + qr8 * 256 + ((kc ^ (qr8 & 7)) << 4) + ko) =
                make_uint2(f2tf(p2), f2tf(p3));
        }
        rs0 += __shfl_xor_sync(0xffffffffu, rs0, 1);
        rs0 += __shfl_xor_sync(0xffffffffu, rs0, 2);
        rs1 += __shfl_xor_sync(0xffffffffu, rs1, 1);
        rs1 += __shfl_xor_sync(0xffffffffu, rs1, 2);
        l0 = l0 * cr0 + rs0;
        l1 = l1 * cr1 + rs1;

#pragma unroll
        for (int j = 0; j < 8; j++) {
            O[j][0] *= cr0; O[j][1] *= cr0;
            O[j][2] *= cr1; O[j][3] *= cr1;
        }
        __syncwarp();   // Ps rows are warp-private; order stores before ldmatrix

        // ---- O += P * V : 8 d-atoms, 8 key-steps ----
#pragma unroll
        for (int s = 0; s < 8; ++s) {
            uint32_t a[4];
            {
                int r = 16 * w + (l & 7) + (((l >> 3) & 1) << 3);
                int cc = (2 * s + (l >> 4)) ^ (r & 7);
                ldsm4(a[0], a[1], a[2], a[3], sb + AT_PS + r * 256 + (cc << 4));
            }
            uint32_t bv[8][2];
#pragma unroll
            for (int p = 0; p < 4; p++) {
                int r = 16 * p + (l & 7) + ((l >> 4) << 3);   // r = d row
                int cc = (2 * s + ((l >> 3) & 1)) ^ (r & 7);
                ldsm4(bv[2*p][0], bv[2*p][1], bv[2*p+1][0], bv[2*p+1][1],
                      sb + AT_VT + r * 256 + (cc << 4));
            }
#pragma unroll
            for (int j = 0; j < 8; j++)
                mma_tf32(O[j], a, bv[j][0], bv[j][1]);
        }
    }

    // ---- epilogue: normalize, write head-merged fp32 ----
    const float inv0 = 1.0f / l0, inv1 = 1.0f / l1;
    const int qr = qb + 16 * w + (l >> 2);
#pragma unroll
    for (int j = 0; j < 8; j++) {
        int col = h * HD + 8 * j + 2 * (l & 3);
        *(float2*)&Aout[((size_t)b * SEQ + qr) * DIMSZ + col] =
            make_float2(O[j][0] * inv0, O[j][1] * inv0);
        *(float2*)&Aout[((size_t)b * SEQ + qr + 8) * DIMSZ + col] =
            make_float2(O[j][2] * inv1, O[j][3] * inv1);
    }
}

// ---------------------------------------------------------------------------
extern "C" void kernel_launch(void* const* d_in, const int* in_sizes, int n_in,
                              void* d_out, int out_size)
{
    (void)in_sizes; (void)n_in; (void)out_size;
    const float* x    = (const float*)d_in[0];
    const float* Wq   = (const float*)d_in[1];
    const float* Wk   = (const float*)d_in[2];
    const float* Wv   = (const float*)d_in[3];
    const float* Wo   = (const float*)d_in[4];
    const int*   mask = (const int*)d_in[5];
    float*       out  = (float*)d_out;

    float *Qp = nullptr, *Kp = nullptr, *Vp = nullptr, *Ap = nullptr;
    cudaGetSymbolAddress((void**)&Qp, g_Q);
    cudaGetSymbolAddress((void**)&Kp, g_K);
    cudaGetSymbolAddress((void**)&Vp, g_V);
    cudaGetSymbolAddress((void**)&Ap, g_A);

    cudaFuncSetAttribute(gemm_tc,
                         cudaFuncAttributeMaxDynamicSharedMemorySize, G_SMEM);
    cudaFuncSetAttribute(attn_tc,
                         cudaFuncAttributeMaxDynamicSharedMemorySize, AT_SMEM);

    dim3 ggrid(DIMSZ / 64, M_TOT / 128);   // (8, 64)
    gemm_tc<<<ggrid, 256, G_SMEM>>>(x, Wq, Qp);
    gemm_tc<<<ggrid, 256, G_SMEM>>>(x, Wk, Kp);
    gemm_tc<<<ggrid, 256, G_SMEM>>>(x, Wv, Vp);

    attn_tc<<<dim3(SEQ / 128, HEADS, BSZ), 256, AT_SMEM>>>(Qp, Kp, Vp, mask, Ap);

    gemm_tc<<<ggrid, 256, G_SMEM>>>(Ap, Wo, out);
}

// round 11
// speedup vs baseline: 1.0008x; 1.0008x over previous
#include <cuda_runtime.h>
#include <cstdint>

// Problem constants
#define BSZ     4
#define SEQ     2048
#define DIMSZ   512
#define HEADS   8
#define HD      64
#define M_TOT   (BSZ * SEQ)   // 8192
#define NEGV    (-1000000.0f)

// Scratch (device globals: allocation rules forbid cudaMalloc)
__device__ float g_Q[M_TOT * DIMSZ];
__device__ float g_K[M_TOT * DIMSZ];
__device__ float g_V[M_TOT * DIMSZ];
__device__ float g_A[M_TOT * DIMSZ];

// ===========================================================================
// Helpers: compute_103-safe PTX only (mma.sync / ldmatrix / cvt.rna.tf32)
// ===========================================================================
__device__ __forceinline__ uint32_t smem_u32(const void* p) {
    uint32_t a;
    asm("{ .reg .u64 t; cvta.to.shared.u64 t, %1; cvt.u32.u64 %0, t; }"
        : "=r"(a) : "l"(p));
    return a;
}

__device__ __forceinline__ uint32_t f2tf(float f) {
    uint32_t u;
    asm("cvt.rna.tf32.f32 %0, %1;" : "=r"(u) : "f"(f));
    return u;
}

__device__ __forceinline__ uint4 cvt4(float4 v) {
    uint4 t;
    t.x = f2tf(v.x); t.y = f2tf(v.y); t.z = f2tf(v.z); t.w = f2tf(v.w);
    return t;
}

__device__ __forceinline__ void ldsm4(uint32_t& r0, uint32_t& r1,
                                      uint32_t& r2, uint32_t& r3,
                                      uint32_t addr) {
    asm volatile("ldmatrix.sync.aligned.m8n8.x4.shared.b16 {%0,%1,%2,%3}, [%4];"
                 : "=r"(r0), "=r"(r1), "=r"(r2), "=r"(r3) : "r"(addr));
}

// D (fp32) += A(tf32 row-major m16 x k8) * B(tf32 col-major k8 x n8)
__device__ __forceinline__ void mma_tf32(float* d, const uint32_t* a,
                                         uint32_t b0, uint32_t b1) {
    asm volatile(
        "mma.sync.aligned.m16n8k8.row.col.f32.tf32.tf32.f32 "
        "{%0,%1,%2,%3}, {%4,%5,%6,%7}, {%8,%9}, {%0,%1,%2,%3};"
        : "+f"(d[0]), "+f"(d[1]), "+f"(d[2]), "+f"(d[3])
        : "r"(a[0]), "r"(a[1]), "r"(a[2]), "r"(a[3]), "r"(b0), "r"(b1));
}

// ===========================================================================
// GEMM:  D[M,512] = A[M,512] * W[512,512]^T   (tf32 mma, fp32 acc)
// CTA tile 128(m) x 64(n), 256 threads, warp tile 32x32, K-chunks of 32.
// SMEM rows = 32 floats (128B, 8 x 16B chunks), xor-swizzled, double-buffered.
// ===========================================================================
#define G_STAGE 24576      // A tile 16KB + W tile 8KB
#define G_SMEM  (2 * G_STAGE)

__global__ __launch_bounds__(256, 2)
void gemm_tc(const float* __restrict__ A, const float* __restrict__ W,
             float* __restrict__ D)
{
    extern __shared__ char sm[];
    const uint32_t sb = smem_u32(sm);
    const int tid = threadIdx.x;
    const int l   = tid & 31;
    const int wid = tid >> 5;
    const int wm  = wid & 3;        // 4 warps along M
    const int wn  = wid >> 2;       // 2 warps along N
    const int rowBase = blockIdx.y * 128;
    const int colBase = blockIdx.x * 64;

    float4 pa[4], pw[2];

    // prefetch chunk c into regs
    auto prefetch = [&](int c) {
#pragma unroll
        for (int i = 0; i < 4; i++) {
            int idx = tid + i * 256;           // 0..1023
            int r = idx >> 3, cc = idx & 7;
            pa[i] = *(const float4*)&A[(size_t)(rowBase + r) * DIMSZ + c * 32 + cc * 4];
        }
#pragma unroll
        for (int i = 0; i < 2; i++) {
            int idx = tid + i * 256;           // 0..511
            int r = idx >> 3, cc = idx & 7;
            pw[i] = *(const float4*)&W[(size_t)(colBase + r) * DIMSZ + c * 32 + cc * 4];
        }
    };
    // store regs into buffer (tf32-converted, swizzled)
    auto stage = [&](int buf) {
        char* base = sm + buf * G_STAGE;
#pragma unroll
        for (int i = 0; i < 4; i++) {
            int idx = tid + i * 256;
            int r = idx >> 3, cc = idx & 7;
            *(uint4*)(base + r * 128 + ((cc ^ (r & 7)) << 4)) = cvt4(pa[i]);
        }
#pragma unroll
        for (int i = 0; i < 2; i++) {
            int idx = tid + i * 256;
            int r = idx >> 3, cc = idx & 7;
            *(uint4*)(base + 16384 + r * 128 + ((cc ^ (r & 7)) << 4)) = cvt4(pw[i]);
        }
    };

    float acc[2][4][4];
#pragma unroll
    for (int im = 0; im < 2; im++)
#pragma unroll
        for (int j = 0; j < 4; j++)
#pragma unroll
            for (int q = 0; q < 4; q++) acc[im][j][q] = 0.f;

    prefetch(0);
    stage(0);

    for (int c = 0; c < 16; ++c) {
        __syncthreads();
        if (c < 15) prefetch(c + 1);
        const uint32_t abase = sb + (c & 1) * G_STAGE;
        const uint32_t wbase = abase + 16384;
#pragma unroll
        for (int s = 0; s < 4; ++s) {
            uint32_t a[2][4];
#pragma unroll
            for (int im = 0; im < 2; im++) {
                int r = 32 * wm + 16 * im + (l & 7) + (((l >> 3) & 1) << 3);
                int cc = (2 * s + (l >> 4)) ^ (r & 7);
                ldsm4(a[im][0], a[im][1], a[im][2], a[im][3],
                      abase + r * 128 + (cc << 4));
            }
            uint32_t b[4][2];
#pragma unroll
            for (int p = 0; p < 2; p++) {
                int r = 32 * wn + 16 * p + (l & 7) + ((l >> 4) << 3);
                int cc = (2 * s + ((l >> 3) & 1)) ^ (r & 7);
                ldsm4(b[2 * p][0], b[2 * p][1], b[2 * p + 1][0], b[2 * p + 1][1],
                      wbase + r * 128 + (cc << 4));
            }
#pragma unroll
            for (int im = 0; im < 2; im++)
#pragma unroll
                for (int j = 0; j < 4; j++)
                    mma_tf32(acc[im][j], a[im], b[j][0], b[j][1]);
        }
        if (c < 15) stage((c + 1) & 1);
    }

    // epilogue
#pragma unroll
    for (int im = 0; im < 2; im++) {
        int r0 = rowBase + 32 * wm + 16 * im + (l >> 2);
#pragma unroll
        for (int j = 0; j < 4; j++) {
            int col = colBase + 32 * wn + 8 * j + 2 * (l & 3);
            *(float2*)&D[(size_t)r0 * DIMSZ + col] =
                make_float2(acc[im][j][0], acc[im][j][1]);
            *(float2*)&D[(size_t)(r0 + 8) * DIMSZ + col] =
                make_float2(acc[im][j][2], acc[im][j][3]);
        }
    }
}

// ===========================================================================
// Fused flash-attention with tf32 mma.sync.
// CTA: 128 q-rows of one (b,h); 8 warps; warp owns 16 q-rows.
// KV tiles of 64.  SMEM rows = 64 floats (256B, 16 chunks), xor-swizzled.
//   Qs[128][64]  (q, d)    pre-scaled by 1/8, tf32
//   Ks[64][64]   (key, d)  tf32
//   Vt[64][64]   (d, key)  tf32 (transposed during staging)
//   Ps[128][64]  (q, key)  tf32
// ===========================================================================
#define AT_QS   0
#define AT_KS   32768
#define AT_VT   49152
#define AT_PS   65536
#define AT_MSK  98304
#define AT_SMEM (98304 + 256)

__global__ __launch_bounds__(256, 2)
void attn_tc(const float* __restrict__ Q, const float* __restrict__ K,
             const float* __restrict__ V, const int* __restrict__ mask,
             float* __restrict__ Aout)
{
    extern __shared__ char sm[];
    const uint32_t sb = smem_u32(sm);
    int* msk = (int*)(sm + AT_MSK);

    const int tid = threadIdx.x;
    const int l   = tid & 31;
    const int w   = tid >> 5;       // warp id: rows 16*w
    const int b   = blockIdx.z;
    const int h   = blockIdx.y;
    const int qb  = blockIdx.x * 128;

    const float* Qb = Q + ((size_t)b * SEQ) * DIMSZ + h * HD;
    const float* Kb = K + ((size_t)b * SEQ) * DIMSZ + h * HD;
    const float* Vb = V + ((size_t)b * SEQ) * DIMSZ + h * HD;
    const int*   mb = mask + b * SEQ;

    // Load Q tile once: (q,d), scaled 1/8, tf32, swizzled
#pragma unroll
    for (int i = 0; i < 8; i++) {
        int idx = tid + i * 256;      // 0..2047
        int r = idx >> 4, cc = idx & 15;
        float4 v = *(const float4*)&Qb[(size_t)(qb + r) * DIMSZ + cc * 4];
        v.x *= 0.125f; v.y *= 0.125f; v.z *= 0.125f; v.w *= 0.125f;
        *(uint4*)(sm + AT_QS + r * 256 + ((cc ^ (r & 7)) << 4)) = cvt4(v);
    }

    float O[8][4];
    float m0 = -1e30f, m1 = -1e30f, l0 = 0.f, l1 = 0.f;
#pragma unroll
    for (int j = 0; j < 8; j++)
#pragma unroll
        for (int q = 0; q < 4; q++) O[j][q] = 0.f;

    for (int k0 = 0; k0 < SEQ; k0 += 64) {
        __syncthreads();   // prev tile's PV reads of Ks/Vt complete
        // stage K (natural) and V (transposed)
#pragma unroll
        for (int i = 0; i < 4; i++) {
            int idx = tid + i * 256;   // 0..1023
            int key = idx >> 4, cc = idx & 15;
            float4 kv = *(const float4*)&Kb[(size_t)(k0 + key) * DIMSZ + cc * 4];
            *(uint4*)(sm + AT_KS + key * 256 + ((cc ^ (key & 7)) << 4)) = cvt4(kv);
            float4 vv = *(const float4*)&Vb[(size_t)(k0 + key) * DIMSZ + cc * 4];
            int d0 = cc * 4;
            int kc = key >> 2, ko = (key & 3) * 4;
            *(uint32_t*)(sm + AT_VT + (d0+0) * 256 + ((kc ^ ((d0+0) & 7)) << 4) + ko) = f2tf(vv.x);
            *(uint32_t*)(sm + AT_VT + (d0+1) * 256 + ((kc ^ ((d0+1) & 7)) << 4) + ko) = f2tf(vv.y);
            *(uint32_t*)(sm + AT_VT + (d0+2) * 256 + ((kc ^ ((d0+2) & 7)) << 4) + ko) = f2tf(vv.z);
            *(uint32_t*)(sm + AT_VT + (d0+3) * 256 + ((kc ^ ((d0+3) & 7)) << 4) + ko) = f2tf(vv.w);
        }
        if (tid < 64) msk[tid] = mb[k0 + tid];
        __syncthreads();

        // ---- S = Qs * Ks^T : warp rows 16w, 8 key-atoms, 8 d-steps ----
        float S[8][4];
#pragma unroll
        for (int j = 0; j < 8; j++)
#pragma unroll
            for (int q = 0; q < 4; q++) S[j][q] = 0.f;

#pragma unroll
        for (int s = 0; s < 8; ++s) {
            uint32_t a[4];
            {
                int r = 16 * w + (l & 7) + (((l >> 3) & 1) << 3);
                int cc = (2 * s + (l >> 4)) ^ (r & 7);
                ldsm4(a[0], a[1], a[2], a[3], sb + AT_QS + r * 256 + (cc << 4));
            }
            uint32_t bq[8][2];
#pragma unroll
            for (int p = 0; p < 4; p++) {
                int r = 16 * p + (l & 7) + ((l >> 4) << 3);
                int cc = (2 * s + ((l >> 3) & 1)) ^ (r & 7);
                ldsm4(bq[2*p][0], bq[2*p][1], bq[2*p+1][0], bq[2*p+1][1],
                      sb + AT_KS + r * 256 + (cc << 4));
            }
#pragma unroll
            for (int j = 0; j < 8; j++)
                mma_tf32(S[j], a, bq[j][0], bq[j][1]);
        }

        // ---- mask (Q pre-scaled, so S already /8) ----
#pragma unroll
        for (int j = 0; j < 8; j++) {
            int kA = 8 * j + 2 * (l & 3);
            int mA = msk[kA], mB = msk[kA + 1];
            S[j][0] = mA ? S[j][0] : NEGV;
            S[j][1] = mB ? S[j][1] : NEGV;
            S[j][2] = mA ? S[j][2] : NEGV;
            S[j][3] = mB ? S[j][3] : NEGV;
        }

        // ---- online softmax (rows l/4 and l/4+8; quad = lanes sharing l/4) ----
        float mx0 = -1e30f, mx1 = -1e30f;
#pragma unroll
        for (int j = 0; j < 8; j++) {
            mx0 = fmaxf(mx0, fmaxf(S[j][0], S[j][1]));
            mx1 = fmaxf(mx1, fmaxf(S[j][2], S[j][3]));
        }
        mx0 = fmaxf(mx0, __shfl_xor_sync(0xffffffffu, mx0, 1));
        mx0 = fmaxf(mx0, __shfl_xor_sync(0xffffffffu, mx0, 2));
        mx1 = fmaxf(mx1, __shfl_xor_sync(0xffffffffu, mx1, 1));
        mx1 = fmaxf(mx1, __shfl_xor_sync(0xffffffffu, mx1, 2));

        float mn0 = fmaxf(m0, mx0), mn1 = fmaxf(m1, mx1);
        float cr0 = __expf(m0 - mn0), cr1 = __expf(m1 - mn1);
        m0 = mn0; m1 = mn1;

        float rs0 = 0.f, rs1 = 0.f;
        const int qr  = 16 * w + (l >> 2);
        const int kAc = 2 * (l & 3);          // key offset within atom
#pragma unroll
        for (int j = 0; j < 8; j++) {
            float p0 = __expf(S[j][0] - mn0);
            float p1 = __expf(S[j][1] - mn0);
            float p2 = __expf(S[j][2] - mn1);
            float p3 = __expf(S[j][3] - mn1);
            rs0 += p0 + p1; rs1 += p2 + p3;
            // store P (tf32) to Ps[q][key]
            int kA = 8 * j + kAc;
            int kc = kA >> 2, ko = (kA & 3) * 4;
            *(uint2*)(sm + AT_PS + qr * 256 + ((kc ^ (qr & 7)) << 4) + ko) =
                make_uint2(f2tf(p0), f2tf(p1));
            int qr8 = qr + 8;
            *(uint2*)(sm + AT_PS + qr8 * 256 + ((kc ^ (qr8 & 7)) << 4) + ko) =
                make_uint2(f2tf(p2), f2tf(p3));
        }
        rs0 += __shfl_xor_sync(0xffffffffu, rs0, 1);
        rs0 += __shfl_xor_sync(0xffffffffu, rs0, 2);
        rs1 += __shfl_xor_sync(0xffffffffu, rs1, 1);
        rs1 += __shfl_xor_sync(0xffffffffu, rs1, 2);
        l0 = l0 * cr0 + rs0;
        l1 = l1 * cr1 + rs1;

#pragma unroll
        for (int j = 0; j < 8; j++) {
            O[j][0] *= cr0; O[j][1] *= cr0;
            O[j][2] *= cr1; O[j][3] *= cr1;
        }
        __syncwarp();   // Ps rows are warp-private; order stores before ldmatrix

        // ---- O += P * V : 8 d-atoms, 8 key-steps ----
#pragma unroll
        for (int s = 0; s < 8; ++s) {
            uint32_t a[4];
            {
                int r = 16 * w + (l & 7) + (((l >> 3) & 1) << 3);
                int cc = (2 * s + (l >> 4)) ^ (r & 7);
                ldsm4(a[0], a[1], a[2], a[3], sb + AT_PS + r * 256 + (cc << 4));
            }
            uint32_t bv[8][2];
#pragma unroll
            for (int p = 0; p < 4; p++) {
                int r = 16 * p + (l & 7) + ((l >> 4) << 3);   // r = d row
                int cc = (2 * s + ((l >> 3) & 1)) ^ (r & 7);
                ldsm4(bv[2*p][0], bv[2*p][1], bv[2*p+1][0], bv[2*p+1][1],
                      sb + AT_VT + r * 256 + (cc << 4));
            }
#pragma unroll
            for (int j = 0; j < 8; j++)
                mma_tf32(O[j], a, bv[j][0], bv[j][1]);
        }
    }

    // ---- epilogue: normalize, write head-merged fp32 ----
    const float inv0 = 1.0f / l0, inv1 = 1.0f / l1;
    const int qr = qb + 16 * w + (l >> 2);
#pragma unroll
    for (int j = 0; j < 8; j++) {
        int col = h * HD + 8 * j + 2 * (l & 3);
        *(float2*)&Aout[((size_t)b * SEQ + qr) * DIMSZ + col] =
            make_float2(O[j][0] * inv0, O[j][1] * inv0);
        *(float2*)&Aout[((size_t)b * SEQ + qr + 8) * DIMSZ + col] =
            make_float2(O[j][2] * inv1, O[j][3] * inv1);
    }
}

// ---------------------------------------------------------------------------
extern "C" void kernel_launch(void* const* d_in, const int* in_sizes, int n_in,
                              void* d_out, int out_size)
{
    (void)in_sizes; (void)n_in; (void)out_size;
    const float* x    = (const float*)d_in[0];
    const float* Wq   = (const float*)d_in[1];
    const float* Wk   = (const float*)d_in[2];
    const float* Wv   = (const float*)d_in[3];
    const float* Wo   = (const float*)d_in[4];
    const int*   mask = (const int*)d_in[5];
    float*       out  = (float*)d_out;

    float *Qp = nullptr, *Kp = nullptr, *Vp = nullptr, *Ap = nullptr;
    cudaGetSymbolAddress((void**)&Qp, g_Q);
    cudaGetSymbolAddress((void**)&Kp, g_K);
    cudaGetSymbolAddress((void**)&Vp, g_V);
    cudaGetSymbolAddress((void**)&Ap, g_A);

    cudaFuncSetAttribute(gemm_tc,
                         cudaFuncAttributeMaxDynamicSharedMemorySize, G_SMEM);
    cudaFuncSetAttribute(attn_tc,
                         cudaFuncAttributeMaxDynamicSharedMemorySize, AT_SMEM);

    dim3 ggrid(DIMSZ / 64, M_TOT / 128);   // (8, 64)
    gemm_tc<<<ggrid, 256, G_SMEM>>>(x, Wq, Qp);
    gemm_tc<<<ggrid, 256, G_SMEM>>>(x, Wk, Kp);
    gemm_tc<<<ggrid, 256, G_SMEM>>>(x, Wv, Vp);

    attn_tc<<<dim3(SEQ / 128, HEADS, BSZ), 256, AT_SMEM>>>(Qp, Kp, Vp, mask, Ap);

    gemm_tc<<<ggrid, 256, G_SMEM>>>(Ap, Wo, out);
}

// round 12
// speedup vs baseline: 1.2362x; 1.2352x over previous
#include <cuda_runtime.h>
#include <cstdint>

// Problem constants
#define BSZ     4
#define SEQ     2048
#define DIMSZ   512
#define HEADS   8
#define HD      64
#define M_TOT   (BSZ * SEQ)   // 8192
#define NEGV    (-1000000.0f)

// Scratch (device globals: allocation rules forbid cudaMalloc)
// g_Q/g_K: tf32-rounded fp32 bits (Q pre-scaled by 1/8), layout [b*SEQ][DIM]
// g_V:     tf32-rounded, TRANSPOSED: [b][dim_full][seq]  (dim_full = h*64+d)
__device__ float g_Q[M_TOT * DIMSZ];
__device__ float g_K[M_TOT * DIMSZ];
__device__ float g_V[M_TOT * DIMSZ];
__device__ float g_A[M_TOT * DIMSZ];

// ===========================================================================
// Helpers: compute_103-safe PTX only (mma.sync / ldmatrix / cvt / cp.async)
// ===========================================================================
__device__ __forceinline__ uint32_t smem_u32(const void* p) {
    uint32_t a;
    asm("{ .reg .u64 t; cvta.to.shared.u64 t, %1; cvt.u32.u64 %0, t; }"
        : "=r"(a) : "l"(p));
    return a;
}

__device__ __forceinline__ uint32_t f2tf(float f) {
    uint32_t u;
    asm("cvt.rna.tf32.f32 %0, %1;" : "=r"(u) : "f"(f));
    return u;
}

__device__ __forceinline__ uint4 cvt4(float4 v) {
    uint4 t;
    t.x = f2tf(v.x); t.y = f2tf(v.y); t.z = f2tf(v.z); t.w = f2tf(v.w);
    return t;
}

__device__ __forceinline__ void ldsm4(uint32_t& r0, uint32_t& r1,
                                      uint32_t& r2, uint32_t& r3,
                                      uint32_t addr) {
    asm volatile("ldmatrix.sync.aligned.m8n8.x4.shared.b16 {%0,%1,%2,%3}, [%4];"
                 : "=r"(r0), "=r"(r1), "=r"(r2), "=r"(r3) : "r"(addr));
}

__device__ __forceinline__ void mma_tf32(float* d, const uint32_t* a,
                                         uint32_t b0, uint32_t b1) {
    asm volatile(
        "mma.sync.aligned.m16n8k8.row.col.f32.tf32.tf32.f32 "
        "{%0,%1,%2,%3}, {%4,%5,%6,%7}, {%8,%9}, {%0,%1,%2,%3};"
        : "+f"(d[0]), "+f"(d[1]), "+f"(d[2]), "+f"(d[3])
        : "r"(a[0]), "r"(a[1]), "r"(a[2]), "r"(a[3]), "r"(b0), "r"(b1));
}

__device__ __forceinline__ void cpa16(uint32_t dst, const void* src) {
    asm volatile("cp.async.cg.shared.global [%0], [%1], 16;"
                 :: "r"(dst), "l"(src) : "memory");
}
#define CP_COMMIT() asm volatile("cp.async.commit_group;" ::: "memory")
#define CP_WAIT1()  asm volatile("cp.async.wait_group 1;" ::: "memory")

// ===========================================================================
// GEMM:  D[M,512] = A[M,512] * W[512,512]^T  (tf32 mma, fp32 acc)
// Inner loops identical to the validated R6 kernel; epilogue templated:
//   EPI 0: plain fp32 store           (final output GEMM)
//   EPI 1: tf32-rounded store         (K projection)
//   EPI 2: tf32-rounded * 0.125      (Q projection, pre-scaled)
//   EPI 3: tf32-rounded + transpose  (V projection -> g_V[b][dim][seq])
// ===========================================================================
#define G_STAGE 24576      // A tile 16KB + W tile 8KB
#define G_SMEM  (2 * G_STAGE)

template<int EPI>
__global__ __launch_bounds__(256, 2)
void gemm_tc(const float* __restrict__ A, const float* __restrict__ W,
             float* __restrict__ D)
{
    extern __shared__ char sm[];
    const uint32_t sb = smem_u32(sm);
    const int tid = threadIdx.x;
    const int l   = tid & 31;
    const int wid = tid >> 5;
    const int wm  = wid & 3;        // 4 warps along M
    const int wn  = wid >> 2;       // 2 warps along N
    const int rowBase = blockIdx.y * 128;
    const int colBase = blockIdx.x * 64;

    float4 pa[4], pw[2];

    auto prefetch = [&](int c) {
#pragma unroll
        for (int i = 0; i < 4; i++) {
            int idx = tid + i * 256;
            int r = idx >> 3, cc = idx & 7;
            pa[i] = *(const float4*)&A[(size_t)(rowBase + r) * DIMSZ + c * 32 + cc * 4];
        }
#pragma unroll
        for (int i = 0; i < 2; i++) {
            int idx = tid + i * 256;
            int r = idx >> 3, cc = idx & 7;
            pw[i] = *(const float4*)&W[(size_t)(colBase + r) * DIMSZ + c * 32 + cc * 4];
        }
    };
    auto stage = [&](int buf) {
        char* base = sm + buf * G_STAGE;
#pragma unroll
        for (int i = 0; i < 4; i++) {
            int idx = tid + i * 256;
            int r = idx >> 3, cc = idx & 7;
            *(uint4*)(base + r * 128 + ((cc ^ (r & 7)) << 4)) = cvt4(pa[i]);
        }
#pragma unroll
        for (int i = 0; i < 2; i++) {
            int idx = tid + i * 256;
            int r = idx >> 3, cc = idx & 7;
            *(uint4*)(base + 16384 + r * 128 + ((cc ^ (r & 7)) << 4)) = cvt4(pw[i]);
        }
    };

    float acc[2][4][4];
#pragma unroll
    for (int im = 0; im < 2; im++)
#pragma unroll
        for (int j = 0; j < 4; j++)
#pragma unroll
            for (int q = 0; q < 4; q++) acc[im][j][q] = 0.f;

    prefetch(0);
    stage(0);

    for (int c = 0; c < 16; ++c) {
        __syncthreads();
        if (c < 15) prefetch(c + 1);
        const uint32_t abase = sb + (c & 1) * G_STAGE;
        const uint32_t wbase = abase + 16384;
#pragma unroll
        for (int s = 0; s < 4; ++s) {
            uint32_t a[2][4];
#pragma unroll
            for (int im = 0; im < 2; im++) {
                int r = 32 * wm + 16 * im + (l & 7) + (((l >> 3) & 1) << 3);
                int cc = (2 * s + (l >> 4)) ^ (r & 7);
                ldsm4(a[im][0], a[im][1], a[im][2], a[im][3],
                      abase + r * 128 + (cc << 4));
            }
            uint32_t b[4][2];
#pragma unroll
            for (int p = 0; p < 2; p++) {
                int r = 32 * wn + 16 * p + (l & 7) + ((l >> 4) << 3);
                int cc = (2 * s + ((l >> 3) & 1)) ^ (r & 7);
                ldsm4(b[2 * p][0], b[2 * p][1], b[2 * p + 1][0], b[2 * p + 1][1],
                      wbase + r * 128 + (cc << 4));
            }
#pragma unroll
            for (int im = 0; im < 2; im++)
#pragma unroll
                for (int j = 0; j < 4; j++)
                    mma_tf32(acc[im][j], a[im], b[j][0], b[j][1]);
        }
        if (c < 15) stage((c + 1) & 1);
    }

    // templated epilogue
#pragma unroll
    for (int im = 0; im < 2; im++) {
        int r0 = rowBase + 32 * wm + 16 * im + (l >> 2);
#pragma unroll
        for (int j = 0; j < 4; j++) {
            int col = colBase + 32 * wn + 8 * j + 2 * (l & 3);
#pragma unroll
            for (int half = 0; half < 2; half++) {
                int r = r0 + 8 * half;
                float v0 = acc[im][j][2 * half];
                float v1 = acc[im][j][2 * half + 1];
                if (EPI == 0) {
                    *(float2*)&D[(size_t)r * DIMSZ + col] = make_float2(v0, v1);
                } else if (EPI == 1) {
                    *(float2*)&D[(size_t)r * DIMSZ + col] =
                        make_float2(__uint_as_float(f2tf(v0)),
                                    __uint_as_float(f2tf(v1)));
                } else if (EPI == 2) {
                    *(float2*)&D[(size_t)r * DIMSZ + col] =
                        make_float2(__uint_as_float(f2tf(v0 * 0.125f)),
                                    __uint_as_float(f2tf(v1 * 0.125f)));
                } else {   // EPI == 3: transpose to [b][dim_full][seq]
                    int bb  = r >> 11;        // r / SEQ
                    int tok = r & (SEQ - 1);
                    D[((size_t)(bb * DIMSZ + col))     * SEQ + tok] =
                        __uint_as_float(f2tf(v0));
                    D[((size_t)(bb * DIMSZ + col + 1)) * SEQ + tok] =
                        __uint_as_float(f2tf(v1));
                }
            }
        }
    }
}

// ===========================================================================
// Fused flash-attention, tf32 mma.sync.
// CTA: 256 q-rows of one (b,h); 8 warps; warp = 32 q-rows (2 m-atoms) x 64 keys.
// cp.async double-buffered K/V/mask staging (inputs pre-rounded/pre-scaled/
// pre-transposed by the projection GEMM epilogues -> staging = raw copies).
// SMEM rows = 64 floats (256B, 16 x 16B chunks), xor-swizzled.
//   Qs[256][64]   (q, d)      at 0        (64KB)
//   Ps[256][64]   (q, key)    at 65536    (64KB)
//   Ks[2][64][64] (key, d)    at 131072   (2 x 16KB)
//   Vt[2][64][64] (d, key)    at 163840   (2 x 16KB)
//   msk[2][64]                at 196608   (2 x 256B)
// ===========================================================================
#define AT_QS   0
#define AT_PS   65536
#define AT_KS   131072
#define AT_VT   163840
#define AT_MSK  196608
#define AT_SMEM 197120

__global__ __launch_bounds__(256, 1)
void attn_tc(const float* __restrict__ Q, const float* __restrict__ K,
             const float* __restrict__ V, const int* __restrict__ mask,
             float* __restrict__ Aout)
{
    extern __shared__ char sm[];
    const uint32_t sb = smem_u32(sm);
    const int tid = threadIdx.x;
    const int l   = tid & 31;
    const int w   = tid >> 5;       // warp id: rows [32w, 32w+32)
    const int b   = blockIdx.z;
    const int h   = blockIdx.y;
    const int qb  = blockIdx.x * 256;

    const float* Qb  = Q + ((size_t)b * SEQ) * DIMSZ + h * HD;
    const float* Kb  = K + ((size_t)b * SEQ) * DIMSZ + h * HD;
    const float* Vtg = V + ((size_t)(b * DIMSZ + h * HD)) * SEQ;  // [d][seq]
    const int*   mb  = mask + b * SEQ;

    // Q tile (once): raw 16B copies, swizzled (bits already tf32, pre-scaled)
#pragma unroll
    for (int i = 0; i < 16; i++) {
        int idx = tid + i * 256;          // 0..4095
        int r = idx >> 4, cc = idx & 15;
        cpa16(sb + AT_QS + r * 256 + ((cc ^ (r & 7)) << 4),
              Qb + (size_t)(qb + r) * DIMSZ + cc * 4);
    }

    auto issue_tile = [&](int t, int buf) {
        const int k0 = t * 64;
#pragma unroll
        for (int i = 0; i < 4; i++) {
            int idx = tid + i * 256;      // 0..1023
            int key = idx >> 4, cc = idx & 15;
            cpa16(sb + AT_KS + buf * 16384 + key * 256 + ((cc ^ (key & 7)) << 4),
                  Kb + (size_t)(k0 + key) * DIMSZ + cc * 4);
        }
#pragma unroll
        for (int i = 0; i < 4; i++) {
            int idx = tid + i * 256;
            int d = idx >> 4, cc = idx & 15;
            cpa16(sb + AT_VT + buf * 16384 + d * 256 + ((cc ^ (d & 7)) << 4),
                  Vtg + (size_t)d * SEQ + k0 + cc * 4);
        }
        if (tid < 16)
            cpa16(sb + AT_MSK + buf * 256 + tid * 16, mb + k0 + tid * 4);
    };

    issue_tile(0, 0); CP_COMMIT();   // group 0: Q + tile 0
    issue_tile(1, 1); CP_COMMIT();   // group 1: tile 1

    float O[2][8][4];
    float mr[4], ls[4];
#pragma unroll
    for (int i = 0; i < 4; i++) { mr[i] = -1e30f; ls[i] = 0.f; }
#pragma unroll
    for (int at = 0; at < 2; at++)
#pragma unroll
        for (int j = 0; j < 8; j++)
#pragma unroll
            for (int q = 0; q < 4; q++) O[at][j][q] = 0.f;

    for (int t = 0; t < 32; t++) {
        const int buf = t & 1;
        CP_WAIT1();
        __syncthreads();
        const uint32_t ksb = sb + AT_KS + buf * 16384;
        const uint32_t vtb = sb + AT_VT + buf * 16384;
        const int* mskp = (const int*)(sm + AT_MSK + buf * 256);

        // ---- S = Qs * Ks^T (both m-atoms share B fragments) ----
        float S[2][8][4];
#pragma unroll
        for (int at = 0; at < 2; at++)
#pragma unroll
            for (int j = 0; j < 8; j++)
#pragma unroll
                for (int q = 0; q < 4; q++) S[at][j][q] = 0.f;

#pragma unroll
        for (int s = 0; s < 8; ++s) {
            uint32_t a0[4], a1[4];
            const int ra  = 32 * w + (l & 7) + (((l >> 3) & 1) << 3);
            const int cca = (2 * s + (l >> 4)) ^ (ra & 7);
            ldsm4(a0[0], a0[1], a0[2], a0[3],
                  sb + AT_QS + ra * 256 + (cca << 4));
            ldsm4(a1[0], a1[1], a1[2], a1[3],
                  sb + AT_QS + (ra + 16) * 256 + (cca << 4));
            uint32_t bq[8][2];
#pragma unroll
            for (int p = 0; p < 4; p++) {
                int r  = 16 * p + (l & 7) + ((l >> 4) << 3);
                int cc = (2 * s + ((l >> 3) & 1)) ^ (r & 7);
                ldsm4(bq[2*p][0], bq[2*p][1], bq[2*p+1][0], bq[2*p+1][1],
                      ksb + r * 256 + (cc << 4));
            }
#pragma unroll
            for (int j = 0; j < 8; j++) {
                mma_tf32(S[0][j], a0, bq[j][0], bq[j][1]);
                mma_tf32(S[1][j], a1, bq[j][0], bq[j][1]);
            }
        }

        // ---- mask (Q pre-scaled by 1/8, so S already scaled) ----
#pragma unroll
        for (int j = 0; j < 8; j++) {
            int kA = 8 * j + 2 * (l & 3);
            int ma = mskp[kA], mb2 = mskp[kA + 1];
#pragma unroll
            for (int at = 0; at < 2; at++) {
                S[at][j][0] = ma  ? S[at][j][0] : NEGV;
                S[at][j][1] = mb2 ? S[at][j][1] : NEGV;
                S[at][j][2] = ma  ? S[at][j][2] : NEGV;
                S[at][j][3] = mb2 ? S[at][j][3] : NEGV;
            }
        }

        // ---- online softmax per m-atom (quad = 4 lanes sharing a row) ----
#pragma unroll
        for (int at = 0; at < 2; at++) {
            float mx0 = -1e30f, mx1 = -1e30f;
#pragma unroll
            for (int j = 0; j < 8; j++) {
                mx0 = fmaxf(mx0, fmaxf(S[at][j][0], S[at][j][1]));
                mx1 = fmaxf(mx1, fmaxf(S[at][j][2], S[at][j][3]));
            }
            mx0 = fmaxf(mx0, __shfl_xor_sync(0xffffffffu, mx0, 1));
            mx0 = fmaxf(mx0, __shfl_xor_sync(0xffffffffu, mx0, 2));
            mx1 = fmaxf(mx1, __shfl_xor_sync(0xffffffffu, mx1, 1));
            mx1 = fmaxf(mx1, __shfl_xor_sync(0xffffffffu, mx1, 2));

            float mn0 = fmaxf(mr[2*at],     mx0);
            float mn1 = fmaxf(mr[2*at + 1], mx1);
            float cr0 = __expf(mr[2*at]     - mn0);
            float cr1 = __expf(mr[2*at + 1] - mn1);
            mr[2*at] = mn0; mr[2*at + 1] = mn1;

            float rs0 = 0.f, rs1 = 0.f;
            const int qr  = 32 * w + 16 * at + (l >> 2);
            const int kAc = 2 * (l & 3);
#pragma unroll
            for (int j = 0; j < 8; j++) {
                float p0 = __expf(S[at][j][0] - mn0);
                float p1 = __expf(S[at][j][1] - mn0);
                float p2 = __expf(S[at][j][2] - mn1);
                float p3 = __expf(S[at][j][3] - mn1);
                rs0 += p0 + p1; rs1 += p2 + p3;
                int kA = 8 * j + kAc;
                int kc = kA >> 2, ko = (kA & 3) * 4;
                *(uint2*)(sm + AT_PS + qr * 256 + ((kc ^ (qr & 7)) << 4) + ko) =
                    make_uint2(f2tf(p0), f2tf(p1));
                int qr8 = qr + 8;
                *(uint2*)(sm + AT_PS + qr8 * 256 + ((kc ^ (qr8 & 7)) << 4) + ko) =
                    make_uint2(f2tf(p2), f2tf(p3));
            }
            rs0 += __shfl_xor_sync(0xffffffffu, rs0, 1);
            rs0 += __shfl_xor_sync(0xffffffffu, rs0, 2);
            rs1 += __shfl_xor_sync(0xffffffffu, rs1, 1);
            rs1 += __shfl_xor_sync(0xffffffffu, rs1, 2);
            ls[2*at]     = ls[2*at]     * cr0 + rs0;
            ls[2*at + 1] = ls[2*at + 1] * cr1 + rs1;

#pragma unroll
            for (int j = 0; j < 8; j++) {
                O[at][j][0] *= cr0; O[at][j][1] *= cr0;
                O[at][j][2] *= cr1; O[at][j][3] *= cr1;
            }
        }
        __syncwarp();   // Ps rows are warp-private; order stores before ldmatrix

        // ---- O += P * V ----
#pragma unroll
        for (int s = 0; s < 8; ++s) {
            uint32_t a0[4], a1[4];
            const int ra  = 32 * w + (l & 7) + (((l >> 3) & 1) << 3);
            const int cca = (2 * s + (l >> 4)) ^ (ra & 7);
            ldsm4(a0[0], a0[1], a0[2], a0[3],
                  sb + AT_PS + ra * 256 + (cca << 4));
            ldsm4(a1[0], a1[1], a1[2], a1[3],
                  sb + AT_PS + (ra + 16) * 256 + (cca << 4));
            uint32_t bv[8][2];
#pragma unroll
            for (int p = 0; p < 4; p++) {
                int r  = 16 * p + (l & 7) + ((l >> 4) << 3);   // r = d row
                int cc = (2 * s + ((l >> 3) & 1)) ^ (r & 7);
                ldsm4(bv[2*p][0], bv[2*p][1], bv[2*p+1][0], bv[2*p+1][1],
                      vtb + r * 256 + (cc << 4));
            }
#pragma unroll
            for (int j = 0; j < 8; j++) {
                mma_tf32(O[0][j], a0, bv[j][0], bv[j][1]);
                mma_tf32(O[1][j], a1, bv[j][0], bv[j][1]);
            }
        }

        __syncthreads();                      // all warps done with buf
        if (t + 2 < 32) issue_tile(t + 2, buf);
        CP_COMMIT();                          // commit (possibly empty) group
    }

    // ---- epilogue: normalize, write head-merged fp32 ----
#pragma unroll
    for (int at = 0; at < 2; at++) {
        const float inv0 = 1.0f / ls[2*at];
        const float inv1 = 1.0f / ls[2*at + 1];
        const int qr = qb + 32 * w + 16 * at + (l >> 2);
#pragma unroll
        for (int j = 0; j < 8; j++) {
            int col = h * HD + 8 * j + 2 * (l & 3);
            *(float2*)&Aout[((size_t)b * SEQ + qr) * DIMSZ + col] =
                make_float2(O[at][j][0] * inv0, O[at][j][1] * inv0);
            *(float2*)&Aout[((size_t)b * SEQ + qr + 8) * DIMSZ + col] =
                make_float2(O[at][j][2] * inv1, O[at][j][3] * inv1);
        }
    }
}

// ---------------------------------------------------------------------------
extern "C" void kernel_launch(void* const* d_in, const int* in_sizes, int n_in,
                              void* d_out, int out_size)
{
    (void)in_sizes; (void)n_in; (void)out_size;
    const float* x    = (const float*)d_in[0];
    const float* Wq   = (const float*)d_in[1];
    const float* Wk   = (const float*)d_in[2];
    const float* Wv   = (const float*)d_in[3];
    const float* Wo   = (const float*)d_in[4];
    const int*   mask = (const int*)d_in[5];
    float*       out  = (float*)d_out;

    float *Qp = nullptr, *Kp = nullptr, *Vp = nullptr, *Ap = nullptr;
    cudaGetSymbolAddress((void**)&Qp, g_Q);
    cudaGetSymbolAddress((void**)&Kp, g_K);
    cudaGetSymbolAddress((void**)&Vp, g_V);
    cudaGetSymbolAddress((void**)&Ap, g_A);

    cudaFuncSetAttribute(gemm_tc<0>,
                         cudaFuncAttributeMaxDynamicSharedMemorySize, G_SMEM);
    cudaFuncSetAttribute(gemm_tc<1>,
                         cudaFuncAttributeMaxDynamicSharedMemorySize, G_SMEM);
    cudaFuncSetAttribute(gemm_tc<2>,
                         cudaFuncAttributeMaxDynamicSharedMemorySize, G_SMEM);
    cudaFuncSetAttribute(gemm_tc<3>,
                         cudaFuncAttributeMaxDynamicSharedMemorySize, G_SMEM);
    cudaFuncSetAttribute(attn_tc,
                         cudaFuncAttributeMaxDynamicSharedMemorySize, AT_SMEM);

    dim3 ggrid(DIMSZ / 64, M_TOT / 128);   // (8, 64)
    gemm_tc<2><<<ggrid, 256, G_SMEM>>>(x, Wq, Qp);   // Q: tf32, pre-scaled 1/8
    gemm_tc<1><<<ggrid, 256, G_SMEM>>>(x, Wk, Kp);   // K: tf32
    gemm_tc<3><<<ggrid, 256, G_SMEM>>>(x, Wv, Vp);   // V: tf32, transposed

    attn_tc<<<dim3(SEQ / 256, HEADS, BSZ), 256, AT_SMEM>>>(Qp, Kp, Vp, mask, Ap);

    gemm_tc<0><<<ggrid, 256, G_SMEM>>>(Ap, Wo, out); // out: plain fp32
}

// round 13
// speedup vs baseline: 1.3567x; 1.0975x over previous
#include <cuda_runtime.h>
#include <cstdint>

// Problem constants
#define BSZ     4
#define SEQ     2048
#define DIMSZ   512
#define HEADS   8
#define HD      64
#define M_TOT   (BSZ * SEQ)   // 8192
#define NEGV    (-1000000.0f)

// Scratch (device globals: allocation rules forbid cudaMalloc)
// g_Q/g_K: tf32-rounded fp32 bits (Q pre-scaled by 1/8), layout [b*SEQ][DIM]
// g_V:     tf32-rounded, TRANSPOSED: [b][dim_full][seq]  (dim_full = h*64+d)
__device__ float g_Q[M_TOT * DIMSZ];
__device__ float g_K[M_TOT * DIMSZ];
__device__ float g_V[M_TOT * DIMSZ];
__device__ float g_A[M_TOT * DIMSZ];

// ===========================================================================
// Helpers: compute_103-safe PTX only (mma.sync / ldmatrix / cvt / cp.async)
// ===========================================================================
__device__ __forceinline__ uint32_t smem_u32(const void* p) {
    uint32_t a;
    asm("{ .reg .u64 t; cvta.to.shared.u64 t, %1; cvt.u32.u64 %0, t; }"
        : "=r"(a) : "l"(p));
    return a;
}

__device__ __forceinline__ uint32_t f2tf(float f) {
    uint32_t u;
    asm("cvt.rna.tf32.f32 %0, %1;" : "=r"(u) : "f"(f));
    return u;
}

__device__ __forceinline__ uint4 cvt4(float4 v) {
    uint4 t;
    t.x = f2tf(v.x); t.y = f2tf(v.y); t.z = f2tf(v.z); t.w = f2tf(v.w);
    return t;
}

__device__ __forceinline__ void ldsm4(uint32_t& r0, uint32_t& r1,
                                      uint32_t& r2, uint32_t& r3,
                                      uint32_t addr) {
    asm volatile("ldmatrix.sync.aligned.m8n8.x4.shared.b16 {%0,%1,%2,%3}, [%4];"
                 : "=r"(r0), "=r"(r1), "=r"(r2), "=r"(r3) : "r"(addr));
}

__device__ __forceinline__ void mma_tf32(float* d, const uint32_t* a,
                                         uint32_t b0, uint32_t b1) {
    asm volatile(
        "mma.sync.aligned.m16n8k8.row.col.f32.tf32.tf32.f32 "
        "{%0,%1,%2,%3}, {%4,%5,%6,%7}, {%8,%9}, {%0,%1,%2,%3};"
        : "+f"(d[0]), "+f"(d[1]), "+f"(d[2]), "+f"(d[3])
        : "r"(a[0]), "r"(a[1]), "r"(a[2]), "r"(a[3]), "r"(b0), "r"(b1));
}

__device__ __forceinline__ void cpa16(uint32_t dst, const void* src) {
    asm volatile("cp.async.cg.shared.global [%0], [%1], 16;"
                 :: "r"(dst), "l"(src) : "memory");
}
#define CP_COMMIT() asm volatile("cp.async.commit_group;" ::: "memory")
#define CP_WAIT1()  asm volatile("cp.async.wait_group 1;" ::: "memory")

// ===========================================================================
// GEMM:  D[M,512] = A[M,512] * W[512,512]^T  (tf32 mma, fp32 acc)
// Inner loops identical to the validated R6 kernel; epilogue templated:
//   EPI 0: plain fp32 store           (final output GEMM)
//   EPI 1: tf32-rounded store         (K projection)
//   EPI 2: tf32-rounded * 0.125      (Q projection, pre-scaled)
//   EPI 3: tf32-rounded + transpose  (V projection -> g_V[b][dim][seq])
// ===========================================================================
#define G_STAGE 24576      // A tile 16KB + W tile 8KB
#define G_SMEM  (2 * G_STAGE)

template<int EPI>
__global__ __launch_bounds__(256, 2)
void gemm_tc(const float* __restrict__ A, const float* __restrict__ W,
             float* __restrict__ D)
{
    extern __shared__ char sm[];
    const uint32_t sb = smem_u32(sm);
    const int tid = threadIdx.x;
    const int l   = tid & 31;
    const int wid = tid >> 5;
    const int wm  = wid & 3;        // 4 warps along M
    const int wn  = wid >> 2;       // 2 warps along N
    const int rowBase = blockIdx.y * 128;
    const int colBase = blockIdx.x * 64;

    float4 pa[4], pw[2];

    auto prefetch = [&](int c) {
#pragma unroll
        for (int i = 0; i < 4; i++) {
            int idx = tid + i * 256;
            int r = idx >> 3, cc = idx & 7;
            pa[i] = *(const float4*)&A[(size_t)(rowBase + r) * DIMSZ + c * 32 + cc * 4];
        }
#pragma unroll
        for (int i = 0; i < 2; i++) {
            int idx = tid + i * 256;
            int r = idx >> 3, cc = idx & 7;
            pw[i] = *(const float4*)&W[(size_t)(colBase + r) * DIMSZ + c * 32 + cc * 4];
        }
    };
    auto stage = [&](int buf) {
        char* base = sm + buf * G_STAGE;
#pragma unroll
        for (int i = 0; i < 4; i++) {
            int idx = tid + i * 256;
            int r = idx >> 3, cc = idx & 7;
            *(uint4*)(base + r * 128 + ((cc ^ (r & 7)) << 4)) = cvt4(pa[i]);
        }
#pragma unroll
        for (int i = 0; i < 2; i++) {
            int idx = tid + i * 256;
            int r = idx >> 3, cc = idx & 7;
            *(uint4*)(base + 16384 + r * 128 + ((cc ^ (r & 7)) << 4)) = cvt4(pw[i]);
        }
    };

    float acc[2][4][4];
#pragma unroll
    for (int im = 0; im < 2; im++)
#pragma unroll
        for (int j = 0; j < 4; j++)
#pragma unroll
            for (int q = 0; q < 4; q++) acc[im][j][q] = 0.f;

    prefetch(0);
    stage(0);

    for (int c = 0; c < 16; ++c) {
        __syncthreads();
        if (c < 15) prefetch(c + 1);
        const uint32_t abase = sb + (c & 1) * G_STAGE;
        const uint32_t wbase = abase + 16384;
#pragma unroll
        for (int s = 0; s < 4; ++s) {
            uint32_t a[2][4];
#pragma unroll
            for (int im = 0; im < 2; im++) {
                int r = 32 * wm + 16 * im + (l & 7) + (((l >> 3) & 1) << 3);
                int cc = (2 * s + (l >> 4)) ^ (r & 7);
                ldsm4(a[im][0], a[im][1], a[im][2], a[im][3],
                      abase + r * 128 + (cc << 4));
            }
            uint32_t b[4][2];
#pragma unroll
            for (int p = 0; p < 2; p++) {
                int r = 32 * wn + 16 * p + (l & 7) + ((l >> 4) << 3);
                int cc = (2 * s + ((l >> 3) & 1)) ^ (r & 7);
                ldsm4(b[2 * p][0], b[2 * p][1], b[2 * p + 1][0], b[2 * p + 1][1],
                      wbase + r * 128 + (cc << 4));
            }
#pragma unroll
            for (int im = 0; im < 2; im++)
#pragma unroll
                for (int j = 0; j < 4; j++)
                    mma_tf32(acc[im][j], a[im], b[j][0], b[j][1]);
        }
        if (c < 15) stage((c + 1) & 1);
    }

    // templated epilogue
#pragma unroll
    for (int im = 0; im < 2; im++) {
        int r0 = rowBase + 32 * wm + 16 * im + (l >> 2);
#pragma unroll
        for (int j = 0; j < 4; j++) {
            int col = colBase + 32 * wn + 8 * j + 2 * (l & 3);
#pragma unroll
            for (int half = 0; half < 2; half++) {
                int r = r0 + 8 * half;
                float v0 = acc[im][j][2 * half];
                float v1 = acc[im][j][2 * half + 1];
                if (EPI == 0) {
                    *(float2*)&D[(size_t)r * DIMSZ + col] = make_float2(v0, v1);
                } else if (EPI == 1) {
                    *(float2*)&D[(size_t)r * DIMSZ + col] =
                        make_float2(__uint_as_float(f2tf(v0)),
                                    __uint_as_float(f2tf(v1)));
                } else if (EPI == 2) {
                    *(float2*)&D[(size_t)r * DIMSZ + col] =
                        make_float2(__uint_as_float(f2tf(v0 * 0.125f)),
                                    __uint_as_float(f2tf(v1 * 0.125f)));
                } else {   // EPI == 3: transpose to [b][dim_full][seq]
                    int bb  = r >> 11;        // r / SEQ
                    int tok = r & (SEQ - 1);
                    D[((size_t)(bb * DIMSZ + col))     * SEQ + tok] =
                        __uint_as_float(f2tf(v0));
                    D[((size_t)(bb * DIMSZ + col + 1)) * SEQ + tok] =
                        __uint_as_float(f2tf(v1));
                }
            }
        }
    }
}

// ===========================================================================
// Fused flash-attention, tf32 mma.sync.
// CTA: 128 q-rows of one (b,h); 4 warps; warp = 32 q-rows (2 m-atoms) x 64 keys.
// Occupancy 2 CTAs/SM (96.5KB smem). P never touches SMEM: the S-accumulator
// fragments are permuted into PV A-fragments with intra-quad shuffles.
// cp.async double-buffered K/V/mask staging; inputs pre-rounded/pre-scaled/
// pre-transposed by the projection GEMM epilogues.
// SMEM rows = 64 floats (256B, 16 x 16B chunks), xor-swizzled.
//   Qs[128][64]   (q, d)      at 0        (32KB)
//   Ks[2][64][64] (key, d)    at 32768    (2 x 16KB)
//   Vt[2][64][64] (d, key)    at 65536    (2 x 16KB)
//   msk[2][64]                at 98304    (2 x 256B)
// ===========================================================================
#define AT_QS   0
#define AT_KS   32768
#define AT_VT   65536
#define AT_MSK  98304
#define AT_SMEM 98816

__global__ __launch_bounds__(128, 2)
void attn_tc(const float* __restrict__ Q, const float* __restrict__ K,
             const float* __restrict__ V, const int* __restrict__ mask,
             float* __restrict__ Aout)
{
    extern __shared__ char sm[];
    const uint32_t sb = smem_u32(sm);
    const int tid = threadIdx.x;
    const int l   = tid & 31;
    const int w   = tid >> 5;       // warp id: rows [32w, 32w+32)
    const int b   = blockIdx.z;
    const int h   = blockIdx.y;
    const int qb  = blockIdx.x * 128;

    const float* Qb  = Q + ((size_t)b * SEQ) * DIMSZ + h * HD;
    const float* Kb  = K + ((size_t)b * SEQ) * DIMSZ + h * HD;
    const float* Vtg = V + ((size_t)(b * DIMSZ + h * HD)) * SEQ;  // [d][seq]
    const int*   mb  = mask + b * SEQ;

    // Q tile (once): raw 16B copies, swizzled (bits already tf32, pre-scaled)
#pragma unroll
    for (int i = 0; i < 16; i++) {
        int idx = tid + i * 128;          // 0..2047
        int r = idx >> 4, cc = idx & 15;
        cpa16(sb + AT_QS + r * 256 + ((cc ^ (r & 7)) << 4),
              Qb + (size_t)(qb + r) * DIMSZ + cc * 4);
    }

    auto issue_tile = [&](int t, int buf) {
        const int k0 = t * 64;
#pragma unroll
        for (int i = 0; i < 8; i++) {
            int idx = tid + i * 128;      // 0..1023
            int key = idx >> 4, cc = idx & 15;
            cpa16(sb + AT_KS + buf * 16384 + key * 256 + ((cc ^ (key & 7)) << 4),
                  Kb + (size_t)(k0 + key) * DIMSZ + cc * 4);
        }
#pragma unroll
        for (int i = 0; i < 8; i++) {
            int idx = tid + i * 128;
            int d = idx >> 4, cc = idx & 15;
            cpa16(sb + AT_VT + buf * 16384 + d * 256 + ((cc ^ (d & 7)) << 4),
                  Vtg + (size_t)d * SEQ + k0 + cc * 4);
        }
        if (tid < 16)
            cpa16(sb + AT_MSK + buf * 256 + tid * 16, mb + k0 + tid * 4);
    };

    issue_tile(0, 0); CP_COMMIT();   // group 0: Q + tile 0
    issue_tile(1, 1); CP_COMMIT();   // group 1: tile 1

    float O[2][8][4];
    float mr[4], ls[4];
#pragma unroll
    for (int i = 0; i < 4; i++) { mr[i] = -1e30f; ls[i] = 0.f; }
#pragma unroll
    for (int at = 0; at < 2; at++)
#pragma unroll
        for (int j = 0; j < 8; j++)
#pragma unroll
            for (int q = 0; q < 4; q++) O[at][j][q] = 0.f;

    // shuffle-permute source lanes (S-accum layout -> A-fragment layout)
    const int src0 = (l & ~3) | ((l & 3) >> 1);
    const int src1 = src0 + 2;
    const bool oddc = (l & 1);

    for (int t = 0; t < 32; t++) {
        const int buf = t & 1;
        CP_WAIT1();
        __syncthreads();
        const uint32_t ksb = sb + AT_KS + buf * 16384;
        const uint32_t vtb = sb + AT_VT + buf * 16384;
        const int* mskp = (const int*)(sm + AT_MSK + buf * 256);

        // ---- S = Qs * Ks^T (both m-atoms share B fragments) ----
        float S[2][8][4];
#pragma unroll
        for (int at = 0; at < 2; at++)
#pragma unroll
            for (int j = 0; j < 8; j++)
#pragma unroll
                for (int q = 0; q < 4; q++) S[at][j][q] = 0.f;

#pragma unroll
        for (int s = 0; s < 8; ++s) {
            uint32_t a0[4], a1[4];
            const int ra  = 32 * w + (l & 7) + (((l >> 3) & 1) << 3);
            const int cca = (2 * s + (l >> 4)) ^ (ra & 7);
            ldsm4(a0[0], a0[1], a0[2], a0[3],
                  sb + AT_QS + ra * 256 + (cca << 4));
            ldsm4(a1[0], a1[1], a1[2], a1[3],
                  sb + AT_QS + (ra + 16) * 256 + (cca << 4));
            uint32_t bq[8][2];
#pragma unroll
            for (int p = 0; p < 4; p++) {
                int r  = 16 * p + (l & 7) + ((l >> 4) << 3);
                int cc = (2 * s + ((l >> 3) & 1)) ^ (r & 7);
                ldsm4(bq[2*p][0], bq[2*p][1], bq[2*p+1][0], bq[2*p+1][1],
                      ksb + r * 256 + (cc << 4));
            }
#pragma unroll
            for (int j = 0; j < 8; j++) {
                mma_tf32(S[0][j], a0, bq[j][0], bq[j][1]);
                mma_tf32(S[1][j], a1, bq[j][0], bq[j][1]);
            }
        }

        // ---- mask (Q pre-scaled by 1/8, so S already scaled) ----
#pragma unroll
        for (int j = 0; j < 8; j++) {
            int kA = 8 * j + 2 * (l & 3);
            int ma = mskp[kA], mb2 = mskp[kA + 1];
#pragma unroll
            for (int at = 0; at < 2; at++) {
                S[at][j][0] = ma  ? S[at][j][0] : NEGV;
                S[at][j][1] = mb2 ? S[at][j][1] : NEGV;
                S[at][j][2] = ma  ? S[at][j][2] : NEGV;
                S[at][j][3] = mb2 ? S[at][j][3] : NEGV;
            }
        }

        // ---- online softmax; exp results kept in S registers (become P) ----
#pragma unroll
        for (int at = 0; at < 2; at++) {
            float mx0 = -1e30f, mx1 = -1e30f;
#pragma unroll
            for (int j = 0; j < 8; j++) {
                mx0 = fmaxf(mx0, fmaxf(S[at][j][0], S[at][j][1]));
                mx1 = fmaxf(mx1, fmaxf(S[at][j][2], S[at][j][3]));
            }
            mx0 = fmaxf(mx0, __shfl_xor_sync(0xffffffffu, mx0, 1));
            mx0 = fmaxf(mx0, __shfl_xor_sync(0xffffffffu, mx0, 2));
            mx1 = fmaxf(mx1, __shfl_xor_sync(0xffffffffu, mx1, 1));
            mx1 = fmaxf(mx1, __shfl_xor_sync(0xffffffffu, mx1, 2));

            float mn0 = fmaxf(mr[2*at],     mx0);
            float mn1 = fmaxf(mr[2*at + 1], mx1);
            float cr0 = __expf(mr[2*at]     - mn0);
            float cr1 = __expf(mr[2*at + 1] - mn1);
            mr[2*at] = mn0; mr[2*at + 1] = mn1;

            float rs0 = 0.f, rs1 = 0.f;
#pragma unroll
            for (int j = 0; j < 8; j++) {
                float p0 = __expf(S[at][j][0] - mn0);
                float p1 = __expf(S[at][j][1] - mn0);
                float p2 = __expf(S[at][j][2] - mn1);
                float p3 = __expf(S[at][j][3] - mn1);
                rs0 += p0 + p1; rs1 += p2 + p3;
                S[at][j][0] = p0; S[at][j][1] = p1;
                S[at][j][2] = p2; S[at][j][3] = p3;
            }
            rs0 += __shfl_xor_sync(0xffffffffu, rs0, 1);
            rs0 += __shfl_xor_sync(0xffffffffu, rs0, 2);
            rs1 += __shfl_xor_sync(0xffffffffu, rs1, 1);
            rs1 += __shfl_xor_sync(0xffffffffu, rs1, 2);
            ls[2*at]     = ls[2*at]     * cr0 + rs0;
            ls[2*at + 1] = ls[2*at + 1] * cr1 + rs1;

#pragma unroll
            for (int j = 0; j < 8; j++) {
                O[at][j][0] *= cr0; O[at][j][1] *= cr0;
                O[at][j][2] *= cr1; O[at][j][3] *= cr1;
            }
        }

        // ---- O += P * V : P A-fragments built by intra-quad shuffles ----
        // S-accum (lane 4r+m holds cols 2m,2m+1) -> A-frag (cols m, m+4):
        //   a0 = P[r, m]   from lane src0 = 4r + (m>>1), reg p0/p1 by m parity
        //   a2 = P[r, m+4] from lane src1 = src0 + 2,     reg p0/p1
        //   a1/a3: rows+8, regs p2/p3.
#pragma unroll
        for (int s = 0; s < 8; ++s) {
            uint32_t af[2][4];
#pragma unroll
            for (int at = 0; at < 2; at++) {
                float p0 = S[at][s][0], p1 = S[at][s][1];
                float p2 = S[at][s][2], p3 = S[at][s][3];
                float e00 = __shfl_sync(0xffffffffu, p0, src0);
                float e01 = __shfl_sync(0xffffffffu, p1, src0);
                float e10 = __shfl_sync(0xffffffffu, p0, src1);
                float e11 = __shfl_sync(0xffffffffu, p1, src1);
                float f00 = __shfl_sync(0xffffffffu, p2, src0);
                float f01 = __shfl_sync(0xffffffffu, p3, src0);
                float f10 = __shfl_sync(0xffffffffu, p2, src1);
                float f11 = __shfl_sync(0xffffffffu, p3, src1);
                af[at][0] = f2tf(oddc ? e01 : e00);
                af[at][2] = f2tf(oddc ? e11 : e10);
                af[at][1] = f2tf(oddc ? f01 : f00);
                af[at][3] = f2tf(oddc ? f11 : f10);
            }
            uint32_t bv[8][2];
#pragma unroll
            for (int p = 0; p < 4; p++) {
                int r  = 16 * p + (l & 7) + ((l >> 4) << 3);   // r = d row
                int cc = (2 * s + ((l >> 3) & 1)) ^ (r & 7);
                ldsm4(bv[2*p][0], bv[2*p][1], bv[2*p+1][0], bv[2*p+1][1],
                      vtb + r * 256 + (cc << 4));
            }
#pragma unroll
            for (int j = 0; j < 8; j++) {
                mma_tf32(O[0][j], af[0], bv[j][0], bv[j][1]);
                mma_tf32(O[1][j], af[1], bv[j][0], bv[j][1]);
            }
        }

        __syncthreads();                      // all warps done with buf
        if (t + 2 < 32) issue_tile(t + 2, buf);
        CP_COMMIT();                          // commit (possibly empty) group
    }

    // ---- epilogue: normalize, write head-merged fp32 ----
#pragma unroll
    for (int at = 0; at < 2; at++) {
        const float inv0 = 1.0f / ls[2*at];
        const float inv1 = 1.0f / ls[2*at + 1];
        const int qr = qb + 32 * w + 16 * at + (l >> 2);
#pragma unroll
        for (int j = 0; j < 8; j++) {
            int col = h * HD + 8 * j + 2 * (l & 3);
            *(float2*)&Aout[((size_t)b * SEQ + qr) * DIMSZ + col] =
                make_float2(O[at][j][0] * inv0, O[at][j][1] * inv0);
            *(float2*)&Aout[((size_t)b * SEQ + qr + 8) * DIMSZ + col] =
                make_float2(O[at][j][2] * inv1, O[at][j][3] * inv1);
        }
    }
}

// ---------------------------------------------------------------------------
extern "C" void kernel_launch(void* const* d_in, const int* in_sizes, int n_in,
                              void* d_out, int out_size)
{
    (void)in_sizes; (void)n_in; (void)out_size;
    const float* x    = (const float*)d_in[0];
    const float* Wq   = (const float*)d_in[1];
    const float* Wk   = (const float*)d_in[2];
    const float* Wv   = (const float*)d_in[3];
    const float* Wo   = (const float*)d_in[4];
    const int*   mask = (const int*)d_in[5];
    float*       out  = (float*)d_out;

    float *Qp = nullptr, *Kp = nullptr, *Vp = nullptr, *Ap = nullptr;
    cudaGetSymbolAddress((void**)&Qp, g_Q);
    cudaGetSymbolAddress((void**)&Kp, g_K);
    cudaGetSymbolAddress((void**)&Vp, g_V);
    cudaGetSymbolAddress((void**)&Ap, g_A);

    cudaFuncSetAttribute(gemm_tc<0>,
                         cudaFuncAttributeMaxDynamicSharedMemorySize, G_SMEM);
    cudaFuncSetAttribute(gemm_tc<1>,
                         cudaFuncAttributeMaxDynamicSharedMemorySize, G_SMEM);
    cudaFuncSetAttribute(gemm_tc<2>,
                         cudaFuncAttributeMaxDynamicSharedMemorySize, G_SMEM);
    cudaFuncSetAttribute(gemm_tc<3>,
                         cudaFuncAttributeMaxDynamicSharedMemorySize, G_SMEM);
    cudaFuncSetAttribute(attn_tc,
                         cudaFuncAttributeMaxDynamicSharedMemorySize, AT_SMEM);

    dim3 ggrid(DIMSZ / 64, M_TOT / 128);   // (8, 64)
    gemm_tc<2><<<ggrid, 256, G_SMEM>>>(x, Wq, Qp);   // Q: tf32, pre-scaled 1/8
    gemm_tc<1><<<ggrid, 256, G_SMEM>>>(x, Wk, Kp);   // K: tf32
    gemm_tc<3><<<ggrid, 256, G_SMEM>>>(x, Wv, Vp);   // V: tf32, transposed

    attn_tc<<<dim3(SEQ / 128, HEADS, BSZ), 128, AT_SMEM>>>(Qp, Kp, Vp, mask, Ap);

    gemm_tc<0><<<ggrid, 256, G_SMEM>>>(Ap, Wo, out); // out: plain fp32
}

// round 14
// speedup vs baseline: 1.5501x; 1.1426x over previous
#include <cuda_runtime.h>
#include <cstdint>

// Problem constants
#define BSZ     4
#define SEQ     2048
#define DIMSZ   512
#define HEADS   8
#define HD      64
#define M_TOT   (BSZ * SEQ)   // 8192
#define NEGV    (-1000000.0f)

// Scratch (device globals: allocation rules forbid cudaMalloc)
// g_Q/g_K: tf32-rounded fp32 bits (Q pre-scaled by 1/8), layout [b*SEQ][DIM]
// g_V:     tf32-rounded, TRANSPOSED: [b][dim_full][seq]
// g_A:     attention output, tf32-rounded bits
// g_X:     x pre-rounded to tf32;  g_W: all four W pre-rounded to tf32
__device__ float g_Q[M_TOT * DIMSZ];
__device__ float g_K[M_TOT * DIMSZ];
__device__ float g_V[M_TOT * DIMSZ];
__device__ float g_A[M_TOT * DIMSZ];
__device__ float g_X[M_TOT * DIMSZ];
__device__ float g_W[4 * DIMSZ * DIMSZ];

// ===========================================================================
// Helpers: compute_103-safe PTX only (mma.sync / ldmatrix / cvt / cp.async)
// ===========================================================================
__device__ __forceinline__ uint32_t smem_u32(const void* p) {
    uint32_t a;
    asm("{ .reg .u64 t; cvta.to.shared.u64 t, %1; cvt.u32.u64 %0, t; }"
        : "=r"(a) : "l"(p));
    return a;
}

__device__ __forceinline__ uint32_t f2tf(float f) {
    uint32_t u;
    asm("cvt.rna.tf32.f32 %0, %1;" : "=r"(u) : "f"(f));
    return u;
}

__device__ __forceinline__ uint4 cvt4(float4 v) {
    uint4 t;
    t.x = f2tf(v.x); t.y = f2tf(v.y); t.z = f2tf(v.z); t.w = f2tf(v.w);
    return t;
}

__device__ __forceinline__ void ldsm4(uint32_t& r0, uint32_t& r1,
                                      uint32_t& r2, uint32_t& r3,
                                      uint32_t addr) {
    asm volatile("ldmatrix.sync.aligned.m8n8.x4.shared.b16 {%0,%1,%2,%3}, [%4];"
                 : "=r"(r0), "=r"(r1), "=r"(r2), "=r"(r3) : "r"(addr));
}

__device__ __forceinline__ void mma_tf32(float* d, const uint32_t* a,
                                         uint32_t b0, uint32_t b1) {
    asm volatile(
        "mma.sync.aligned.m16n8k8.row.col.f32.tf32.tf32.f32 "
        "{%0,%1,%2,%3}, {%4,%5,%6,%7}, {%8,%9}, {%0,%1,%2,%3};"
        : "+f"(d[0]), "+f"(d[1]), "+f"(d[2]), "+f"(d[3])
        : "r"(a[0]), "r"(a[1]), "r"(a[2]), "r"(a[3]), "r"(b0), "r"(b1));
}

__device__ __forceinline__ void cpa16(uint32_t dst, const void* src) {
    asm volatile("cp.async.cg.shared.global [%0], [%1], 16;"
                 :: "r"(dst), "l"(src) : "memory");
}
#define CP_COMMIT() asm volatile("cp.async.commit_group;" ::: "memory")
#define CP_WAIT1()  asm volatile("cp.async.wait_group 1;" ::: "memory")

// ===========================================================================
// Prep: round x and the four W matrices to tf32 once (float4 grid-stride).
// ===========================================================================
#define XN4  (M_TOT * DIMSZ / 4)     // 1048576
#define WN4  (DIMSZ * DIMSZ / 4)     // 65536
#define PREP_TOT (XN4 + 4 * WN4)     // 1310720

__global__ void prep_tf32(const float* __restrict__ x,
                          const float* __restrict__ wq,
                          const float* __restrict__ wk,
                          const float* __restrict__ wv,
                          const float* __restrict__ wo,
                          float* __restrict__ gx, float* __restrict__ gw)
{
    int i = blockIdx.x * 256 + threadIdx.x;
    if (i >= PREP_TOT) return;
    const float4* src;
    float4* dst;
    int off;
    if (i < XN4) {
        src = (const float4*)x; dst = (float4*)gx; off = i;
    } else {
        int j = i - XN4;
        int which = j >> 16;          // j / WN4
        off = j & (WN4 - 1);
        const float* ws = (which == 0) ? wq : (which == 1) ? wk
                        : (which == 2) ? wv : wo;
        src = (const float4*)ws;
        dst = (float4*)(gw + (size_t)which * DIMSZ * DIMSZ);
    }
    float4 v = src[off];
    uint4 t = cvt4(v);
    dst[off] = *reinterpret_cast<float4*>(&t);
}

// ===========================================================================
// Shared GEMM mainloop:  acc[2][8][4] += A[128,512] * W[512,512]^T tile
// CTA tile 128(m) x 128(n), 8 warps (4 M x 2 N), warp tile 32x64.
// Operands are pre-rounded tf32 bits -> staging is raw cp.async copies.
// SMEM/stage: A 16KB + W 16KB; double-buffered (64KB total) -> occ 2.
// Rows are 32 tf32 = 128B = 8 x 16B chunks, xor-swizzled.
// ===========================================================================
#define G2_STAGE 32768
#define G2_SMEM  (2 * G2_STAGE)

__device__ __forceinline__ void gemm_core(
    const float* __restrict__ A, const float* __restrict__ W,
    uint32_t sb, int rowBase, int colBase,
    int tid, int l, int wm, int wn, float acc[2][8][4])
{
    auto issue = [&](int c, int buf) {
        const uint32_t base = sb + buf * G2_STAGE;
#pragma unroll
        for (int i = 0; i < 4; i++) {
            int idx = tid + i * 256;          // 0..1023
            int r = idx >> 3, cc = idx & 7;
            cpa16(base + r * 128 + ((cc ^ (r & 7)) << 4),
                  A + (size_t)(rowBase + r) * DIMSZ + c * 32 + cc * 4);
        }
#pragma unroll
        for (int i = 0; i < 4; i++) {
            int idx = tid + i * 256;
            int r = idx >> 3, cc = idx & 7;
            cpa16(base + 16384 + r * 128 + ((cc ^ (r & 7)) << 4),
                  W + (size_t)(colBase + r) * DIMSZ + c * 32 + cc * 4);
        }
    };

    issue(0, 0); CP_COMMIT();
    issue(1, 1); CP_COMMIT();

    for (int c = 0; c < 16; ++c) {
        const int buf = c & 1;
        CP_WAIT1();
        __syncthreads();
        const uint32_t ab = sb + buf * G2_STAGE;
        const uint32_t wb = ab + 16384;
#pragma unroll
        for (int s = 0; s < 4; ++s) {
            uint32_t a[2][4];
            const int ra  = 32 * wm + (l & 7) + (((l >> 3) & 1) << 3);
            const int cca = (2 * s + (l >> 4)) ^ (ra & 7);
            ldsm4(a[0][0], a[0][1], a[0][2], a[0][3],
                  ab + ra * 128 + (cca << 4));
            ldsm4(a[1][0], a[1][1], a[1][2], a[1][3],
                  ab + (ra + 16) * 128 + (cca << 4));
            uint32_t b[8][2];
#pragma unroll
            for (int p = 0; p < 4; p++) {
                int r  = 64 * wn + 16 * p + (l & 7) + ((l >> 4) << 3);
                int cc = (2 * s + ((l >> 3) & 1)) ^ (r & 7);
                ldsm4(b[2*p][0], b[2*p][1], b[2*p+1][0], b[2*p+1][1],
                      wb + r * 128 + (cc << 4));
            }
#pragma unroll
            for (int j = 0; j < 8; j++) {
                mma_tf32(acc[0][j], a[0], b[j][0], b[j][1]);
                mma_tf32(acc[1][j], a[1], b[j][0], b[j][1]);
            }
        }
        __syncthreads();
        if (c + 2 < 16) issue(c + 2, buf);
        CP_COMMIT();
    }
}

// Merged Q/K/V projection GEMM: blockIdx.z selects weight, dst, epilogue.
//   z=0: Q = tf32(acc * 0.125)          z=1: K = tf32(acc)
//   z=2: V = tf32(acc), transposed to [b][dim][seq]
__global__ __launch_bounds__(256, 2)
void proj_gemm(const float* __restrict__ X, const float* __restrict__ Wall,
               float* __restrict__ Qd, float* __restrict__ Kd,
               float* __restrict__ Vd)
{
    extern __shared__ char sm[];
    const uint32_t sb = smem_u32(sm);
    const int tid = threadIdx.x, l = tid & 31, wid = tid >> 5;
    const int wm = wid & 3, wn = wid >> 2;
    const int rowBase = blockIdx.y * 128, colBase = blockIdx.x * 128;
    const int z = blockIdx.z;
    const float* W = Wall + (size_t)z * DIMSZ * DIMSZ;

    float acc[2][8][4];
#pragma unroll
    for (int at = 0; at < 2; at++)
#pragma unroll
        for (int j = 0; j < 8; j++)
#pragma unroll
            for (int q = 0; q < 4; q++) acc[at][j][q] = 0.f;

    gemm_core(X, W, sb, rowBase, colBase, tid, l, wm, wn, acc);

    float* D = (z == 0) ? Qd : (z == 1) ? Kd : Vd;
#pragma unroll
    for (int at = 0; at < 2; at++) {
        int r0 = rowBase + 32 * wm + 16 * at + (l >> 2);
#pragma unroll
        for (int j = 0; j < 8; j++) {
            int col = colBase + 64 * wn + 8 * j + 2 * (l & 3);
#pragma unroll
            for (int half = 0; half < 2; half++) {
                int r = r0 + 8 * half;
                float v0 = acc[at][j][2 * half];
                float v1 = acc[at][j][2 * half + 1];
                if (z == 0) {
                    *(float2*)&D[(size_t)r * DIMSZ + col] =
                        make_float2(__uint_as_float(f2tf(v0 * 0.125f)),
                                    __uint_as_float(f2tf(v1 * 0.125f)));
                } else if (z == 1) {
                    *(float2*)&D[(size_t)r * DIMSZ + col] =
                        make_float2(__uint_as_float(f2tf(v0)),
                                    __uint_as_float(f2tf(v1)));
                } else {
                    int bb  = r >> 11;          // r / SEQ
                    int tok = r & (SEQ - 1);
                    D[((size_t)(bb * DIMSZ + col))     * SEQ + tok] =
                        __uint_as_float(f2tf(v0));
                    D[((size_t)(bb * DIMSZ + col + 1)) * SEQ + tok] =
                        __uint_as_float(f2tf(v1));
                }
            }
        }
    }
}

// Output GEMM: out = g_A (tf32 bits) * Wo^T, plain fp32 store.
__global__ __launch_bounds__(256, 2)
void gemm_out(const float* __restrict__ A, const float* __restrict__ W,
              float* __restrict__ D)
{
    extern __shared__ char sm[];
    const uint32_t sb = smem_u32(sm);
    const int tid = threadIdx.x, l = tid & 31, wid = tid >> 5;
    const int wm = wid & 3, wn = wid >> 2;
    const int rowBase = blockIdx.y * 128, colBase = blockIdx.x * 128;

    float acc[2][8][4];
#pragma unroll
    for (int at = 0; at < 2; at++)
#pragma unroll
        for (int j = 0; j < 8; j++)
#pragma unroll
            for (int q = 0; q < 4; q++) acc[at][j][q] = 0.f;

    gemm_core(A, W, sb, rowBase, colBase, tid, l, wm, wn, acc);

#pragma unroll
    for (int at = 0; at < 2; at++) {
        int r0 = rowBase + 32 * wm + 16 * at + (l >> 2);
#pragma unroll
        for (int j = 0; j < 8; j++) {
            int col = colBase + 64 * wn + 8 * j + 2 * (l & 3);
            *(float2*)&D[(size_t)r0 * DIMSZ + col] =
                make_float2(acc[at][j][0], acc[at][j][1]);
            *(float2*)&D[(size_t)(r0 + 8) * DIMSZ + col] =
                make_float2(acc[at][j][2], acc[at][j][3]);
        }
    }
}

// ===========================================================================
// Fused flash-attention, tf32 mma.sync — IDENTICAL to R13 except the
// epilogue stores tf32-rounded bits (feeds gemm_out's raw-copy staging;
// f2tf is idempotent so the final product is bit-identical to R13).
// ===========================================================================
#define AT_QS   0
#define AT_KS   32768
#define AT_VT   65536
#define AT_MSK  98304
#define AT_SMEM 98816

__global__ __launch_bounds__(128, 2)
void attn_tc(const float* __restrict__ Q, const float* __restrict__ K,
             const float* __restrict__ V, const int* __restrict__ mask,
             float* __restrict__ Aout)
{
    extern __shared__ char sm[];
    const uint32_t sb = smem_u32(sm);
    const int tid = threadIdx.x;
    const int l   = tid & 31;
    const int w   = tid >> 5;
    const int b   = blockIdx.z;
    const int h   = blockIdx.y;
    const int qb  = blockIdx.x * 128;

    const float* Qb  = Q + ((size_t)b * SEQ) * DIMSZ + h * HD;
    const float* Kb  = K + ((size_t)b * SEQ) * DIMSZ + h * HD;
    const float* Vtg = V + ((size_t)(b * DIMSZ + h * HD)) * SEQ;
    const int*   mb  = mask + b * SEQ;

#pragma unroll
    for (int i = 0; i < 16; i++) {
        int idx = tid + i * 128;
        int r = idx >> 4, cc = idx & 15;
        cpa16(sb + AT_QS + r * 256 + ((cc ^ (r & 7)) << 4),
              Qb + (size_t)(qb + r) * DIMSZ + cc * 4);
    }

    auto issue_tile = [&](int t, int buf) {
        const int k0 = t * 64;
#pragma unroll
        for (int i = 0; i < 8; i++) {
            int idx = tid + i * 128;
            int key = idx >> 4, cc = idx & 15;
            cpa16(sb + AT_KS + buf * 16384 + key * 256 + ((cc ^ (key & 7)) << 4),
                  Kb + (size_t)(k0 + key) * DIMSZ + cc * 4);
        }
#pragma unroll
        for (int i = 0; i < 8; i++) {
            int idx = tid + i * 128;
            int d = idx >> 4, cc = idx & 15;
            cpa16(sb + AT_VT + buf * 16384 + d * 256 + ((cc ^ (d & 7)) << 4),
                  Vtg + (size_t)d * SEQ + k0 + cc * 4);
        }
        if (tid < 16)
            cpa16(sb + AT_MSK + buf * 256 + tid * 16, mb + k0 + tid * 4);
    };

    issue_tile(0, 0); CP_COMMIT();
    issue_tile(1, 1); CP_COMMIT();

    float O[2][8][4];
    float mr[4], ls[4];
#pragma unroll
    for (int i = 0; i < 4; i++) { mr[i] = -1e30f; ls[i] = 0.f; }
#pragma unroll
    for (int at = 0; at < 2; at++)
#pragma unroll
        for (int j = 0; j < 8; j++)
#pragma unroll
            for (int q = 0; q < 4; q++) O[at][j][q] = 0.f;

    const int src0 = (l & ~3) | ((l & 3) >> 1);
    const int src1 = src0 + 2;
    const bool oddc = (l & 1);

    for (int t = 0; t < 32; t++) {
        const int buf = t & 1;
        CP_WAIT1();
        __syncthreads();
        const uint32_t ksb = sb + AT_KS + buf * 16384;
        const uint32_t vtb = sb + AT_VT + buf * 16384;
        const int* mskp = (const int*)(sm + AT_MSK + buf * 256);

        float S[2][8][4];
#pragma unroll
        for (int at = 0; at < 2; at++)
#pragma unroll
            for (int j = 0; j < 8; j++)
#pragma unroll
                for (int q = 0; q < 4; q++) S[at][j][q] = 0.f;

#pragma unroll
        for (int s = 0; s < 8; ++s) {
            uint32_t a0[4], a1[4];
            const int ra  = 32 * w + (l & 7) + (((l >> 3) & 1) << 3);
            const int cca = (2 * s + (l >> 4)) ^ (ra & 7);
            ldsm4(a0[0], a0[1], a0[2], a0[3],
                  sb + AT_QS + ra * 256 + (cca << 4));
            ldsm4(a1[0], a1[1], a1[2], a1[3],
                  sb + AT_QS + (ra + 16) * 256 + (cca << 4));
            uint32_t bq[8][2];
#pragma unroll
            for (int p = 0; p < 4; p++) {
                int r  = 16 * p + (l & 7) + ((l >> 4) << 3);
                int cc = (2 * s + ((l >> 3) & 1)) ^ (r & 7);
                ldsm4(bq[2*p][0], bq[2*p][1], bq[2*p+1][0], bq[2*p+1][1],
                      ksb + r * 256 + (cc << 4));
            }
#pragma unroll
            for (int j = 0; j < 8; j++) {
                mma_tf32(S[0][j], a0, bq[j][0], bq[j][1]);
                mma_tf32(S[1][j], a1, bq[j][0], bq[j][1]);
            }
        }

#pragma unroll
        for (int j = 0; j < 8; j++) {
            int kA = 8 * j + 2 * (l & 3);
            int ma = mskp[kA], mb2 = mskp[kA + 1];
#pragma unroll
            for (int at = 0; at < 2; at++) {
                S[at][j][0] = ma  ? S[at][j][0] : NEGV;
                S[at][j][1] = mb2 ? S[at][j][1] : NEGV;
                S[at][j][2] = ma  ? S[at][j][2] : NEGV;
                S[at][j][3] = mb2 ? S[at][j][3] : NEGV;
            }
        }

#pragma unroll
        for (int at = 0; at < 2; at++) {
            float mx0 = -1e30f, mx1 = -1e30f;
#pragma unroll
            for (int j = 0; j < 8; j++) {
                mx0 = fmaxf(mx0, fmaxf(S[at][j][0], S[at][j][1]));
                mx1 = fmaxf(mx1, fmaxf(S[at][j][2], S[at][j][3]));
            }
            mx0 = fmaxf(mx0, __shfl_xor_sync(0xffffffffu, mx0, 1));
            mx0 = fmaxf(mx0, __shfl_xor_sync(0xffffffffu, mx0, 2));
            mx1 = fmaxf(mx1, __shfl_xor_sync(0xffffffffu, mx1, 1));
            mx1 = fmaxf(mx1, __shfl_xor_sync(0xffffffffu, mx1, 2));

            float mn0 = fmaxf(mr[2*at],     mx0);
            float mn1 = fmaxf(mr[2*at + 1], mx1);
            float cr0 = __expf(mr[2*at]     - mn0);
            float cr1 = __expf(mr[2*at + 1] - mn1);
            mr[2*at] = mn0; mr[2*at + 1] = mn1;

            float rs0 = 0.f, rs1 = 0.f;
#pragma unroll
            for (int j = 0; j < 8; j++) {
                float p0 = __expf(S[at][j][0] - mn0);
                float p1 = __expf(S[at][j][1] - mn0);
                float p2 = __expf(S[at][j][2] - mn1);
                float p3 = __expf(S[at][j][3] - mn1);
                rs0 += p0 + p1; rs1 += p2 + p3;
                S[at][j][0] = p0; S[at][j][1] = p1;
                S[at][j][2] = p2; S[at][j][3] = p3;
            }
            rs0 += __shfl_xor_sync(0xffffffffu, rs0, 1);
            rs0 += __shfl_xor_sync(0xffffffffu, rs0, 2);
            rs1 += __shfl_xor_sync(0xffffffffu, rs1, 1);
            rs1 += __shfl_xor_sync(0xffffffffu, rs1, 2);
            ls[2*at]     = ls[2*at]     * cr0 + rs0;
            ls[2*at + 1] = ls[2*at + 1] * cr1 + rs1;

#pragma unroll
            for (int j = 0; j < 8; j++) {
                O[at][j][0] *= cr0; O[at][j][1] *= cr0;
                O[at][j][2] *= cr1; O[at][j][3] *= cr1;
            }
        }

#pragma unroll
        for (int s = 0; s < 8; ++s) {
            uint32_t af[2][4];
#pragma unroll
            for (int at = 0; at < 2; at++) {
                float p0 = S[at][s][0], p1 = S[at][s][1];
                float p2 = S[at][s][2], p3 = S[at][s][3];
                float e00 = __shfl_sync(0xffffffffu, p0, src0);
                float e01 = __shfl_sync(0xffffffffu, p1, src0);
                float e10 = __shfl_sync(0xffffffffu, p0, src1);
                float e11 = __shfl_sync(0xffffffffu, p1, src1);
                float f00 = __shfl_sync(0xffffffffu, p2, src0);
                float f01 = __shfl_sync(0xffffffffu, p3, src0);
                float f10 = __shfl_sync(0xffffffffu, p2, src1);
                float f11 = __shfl_sync(0xffffffffu, p3, src1);
                af[at][0] = f2tf(oddc ? e01 : e00);
                af[at][2] = f2tf(oddc ? e11 : e10);
                af[at][1] = f2tf(oddc ? f01 : f00);
                af[at][3] = f2tf(oddc ? f11 : f10);
            }
            uint32_t bv[8][2];
#pragma unroll
            for (int p = 0; p < 4; p++) {
                int r  = 16 * p + (l & 7) + ((l >> 4) << 3);
                int cc = (2 * s + ((l >> 3) & 1)) ^ (r & 7);
                ldsm4(bv[2*p][0], bv[2*p][1], bv[2*p+1][0], bv[2*p+1][1],
                      vtb + r * 256 + (cc << 4));
            }
#pragma unroll
            for (int j = 0; j < 8; j++) {
                mma_tf32(O[0][j], af[0], bv[j][0], bv[j][1]);
                mma_tf32(O[1][j], af[1], bv[j][0], bv[j][1]);
            }
        }

        __syncthreads();
        if (t + 2 < 32) issue_tile(t + 2, buf);
        CP_COMMIT();
    }

    // epilogue: normalize, tf32-round (feeds gemm_out raw-copy staging)
#pragma unroll
    for (int at = 0; at < 2; at++) {
        const float inv0 = 1.0f / ls[2*at];
        const float inv1 = 1.0f / ls[2*at + 1];
        const int qr = qb + 32 * w + 16 * at + (l >> 2);
#pragma unroll
        for (int j = 0; j < 8; j++) {
            int col = h * HD + 8 * j + 2 * (l & 3);
            *(float2*)&Aout[((size_t)b * SEQ + qr) * DIMSZ + col] =
                make_float2(__uint_as_float(f2tf(O[at][j][0] * inv0)),
                            __uint_as_float(f2tf(O[at][j][1] * inv0)));
            *(float2*)&Aout[((size_t)b * SEQ + qr + 8) * DIMSZ + col] =
                make_float2(__uint_as_float(f2tf(O[at][j][2] * inv1)),
                            __uint_as_float(f2tf(O[at][j][3] * inv1)));
        }
    }
}

// ---------------------------------------------------------------------------
extern "C" void kernel_launch(void* const* d_in, const int* in_sizes, int n_in,
                              void* d_out, int out_size)
{
    (void)in_sizes; (void)n_in; (void)out_size;
    const float* x    = (const float*)d_in[0];
    const float* Wq   = (const float*)d_in[1];
    const float* Wk   = (const float*)d_in[2];
    const float* Wv   = (const float*)d_in[3];
    const float* Wo   = (const float*)d_in[4];
    const int*   mask = (const int*)d_in[5];
    float*       out  = (float*)d_out;

    float *Qp, *Kp, *Vp, *Ap, *Xp, *Wp;
    cudaGetSymbolAddress((void**)&Qp, g_Q);
    cudaGetSymbolAddress((void**)&Kp, g_K);
    cudaGetSymbolAddress((void**)&Vp, g_V);
    cudaGetSymbolAddress((void**)&Ap, g_A);
    cudaGetSymbolAddress((void**)&Xp, g_X);
    cudaGetSymbolAddress((void**)&Wp, g_W);

    cudaFuncSetAttribute(proj_gemm,
                         cudaFuncAttributeMaxDynamicSharedMemorySize, G2_SMEM);
    cudaFuncSetAttribute(gemm_out,
                         cudaFuncAttributeMaxDynamicSharedMemorySize, G2_SMEM);
    cudaFuncSetAttribute(attn_tc,
                         cudaFuncAttributeMaxDynamicSharedMemorySize, AT_SMEM);

    prep_tf32<<<(PREP_TOT + 255) / 256, 256>>>(x, Wq, Wk, Wv, Wo, Xp, Wp);

    proj_gemm<<<dim3(DIMSZ / 128, M_TOT / 128, 3), 256, G2_SMEM>>>(
        Xp, Wp, Qp, Kp, Vp);

    attn_tc<<<dim3(SEQ / 128, HEADS, BSZ), 128, AT_SMEM>>>(Qp, Kp, Vp, mask, Ap);

    gemm_out<<<dim3(DIMSZ / 128, M_TOT / 128), 256, G2_SMEM>>>(
        Ap, Wp + (size_t)3 * DIMSZ * DIMSZ, out);
}

// round 15
// speedup vs baseline: 2.1746x; 1.4029x over previous
#include <cuda_runtime.h>
#include <cstdint>

// Problem constants
#define BSZ     4
#define SEQ     2048
#define DIMSZ   512
#define HEADS   8
#define HD      64
#define M_TOT   (BSZ * SEQ)   // 8192
#define NEGV    (-1000000.0f)

// Scratch (device globals: allocation rules forbid cudaMalloc)
// g_Q:  tf32 bits, pre-scaled by 1/8, [b*SEQ][DIM]
// g_K:  tf32 bits, KEY-COMPACTED rows: row j of batch b = K[b][idx_j]
// g_V:  tf32 bits, transposed AND key-compacted: [b][dim][j]
// g_A:  attention output, tf32 bits
// g_X/g_W: tf32-pre-rounded inputs
__device__ float g_Q[M_TOT * DIMSZ];
__device__ float g_K[M_TOT * DIMSZ];
__device__ float g_V[M_TOT * DIMSZ];
__device__ float g_A[M_TOT * DIMSZ];
__device__ float g_X[M_TOT * DIMSZ];
__device__ float g_W[4 * DIMSZ * DIMSZ];
__device__ int   g_r2c[M_TOT];     // tok -> compacted rank (-1 if masked)
__device__ int   g_cnt[BSZ];       // unmasked keys per batch

// ===========================================================================
// Helpers: compute_103-safe PTX only (mma.sync / ldmatrix / cvt / cp.async)
// ===========================================================================
__device__ __forceinline__ uint32_t smem_u32(const void* p) {
    uint32_t a;
    asm("{ .reg .u64 t; cvta.to.shared.u64 t, %1; cvt.u32.u64 %0, t; }"
        : "=r"(a) : "l"(p));
    return a;
}

__device__ __forceinline__ uint32_t f2tf(float f) {
    uint32_t u;
    asm("cvt.rna.tf32.f32 %0, %1;" : "=r"(u) : "f"(f));
    return u;
}

__device__ __forceinline__ uint4 cvt4(float4 v) {
    uint4 t;
    t.x = f2tf(v.x); t.y = f2tf(v.y); t.z = f2tf(v.z); t.w = f2tf(v.w);
    return t;
}

__device__ __forceinline__ void ldsm4(uint32_t& r0, uint32_t& r1,
                                      uint32_t& r2, uint32_t& r3,
                                      uint32_t addr) {
    asm volatile("ldmatrix.sync.aligned.m8n8.x4.shared.b16 {%0,%1,%2,%3}, [%4];"
                 : "=r"(r0), "=r"(r1), "=r"(r2), "=r"(r3) : "r"(addr));
}

__device__ __forceinline__ void mma_tf32(float* d, const uint32_t* a,
                                         uint32_t b0, uint32_t b1) {
    asm volatile(
        "mma.sync.aligned.m16n8k8.row.col.f32.tf32.tf32.f32 "
        "{%0,%1,%2,%3}, {%4,%5,%6,%7}, {%8,%9}, {%0,%1,%2,%3};"
        : "+f"(d[0]), "+f"(d[1]), "+f"(d[2]), "+f"(d[3])
        : "r"(a[0]), "r"(a[1]), "r"(a[2]), "r"(a[3]), "r"(b0), "r"(b1));
}

__device__ __forceinline__ void cpa16(uint32_t dst, const void* src) {
    asm volatile("cp.async.cg.shared.global [%0], [%1], 16;"
                 :: "r"(dst), "l"(src) : "memory");
}
#define CP_COMMIT() asm volatile("cp.async.commit_group;" ::: "memory")
#define CP_WAIT1()  asm volatile("cp.async.wait_group 1;" ::: "memory")

// ===========================================================================
// mask_scan: deterministic per-batch prefix scan of the key mask.
// r2c[b][tok] = rank among unmasked (ascending tok order), or -1.
// ===========================================================================
__global__ void mask_scan(const int* __restrict__ mask,
                          int* __restrict__ r2c, int* __restrict__ cnt)
{
    __shared__ int ssum[256];
    const int b = blockIdx.x, tid = threadIdx.x;
    const int* mb = mask + b * SEQ;
    const int base = tid * 8;
    int loc[8]; int s = 0;
#pragma unroll
    for (int k = 0; k < 8; k++) { loc[k] = s; s += (mb[base + k] == 1); }
    ssum[tid] = s;
    __syncthreads();
    if (tid == 0) {
        int acc = 0;
        for (int i = 0; i < 256; i++) { int t = ssum[i]; ssum[i] = acc; acc += t; }
        cnt[b] = acc;
    }
    __syncthreads();
    const int off = ssum[tid];
#pragma unroll
    for (int k = 0; k < 8; k++) {
        int tok = base + k;
        r2c[b * SEQ + tok] = (mb[tok] == 1) ? (off + loc[k]) : -1;
    }
}

// Zero the pad strip [cnt, ceil64(cnt)) of compacted K rows and V columns,
// so prefetched pad data is finite (PV multiplies it by exactly-zero P).
__global__ void zero_pad(float* __restrict__ Kc, float* __restrict__ Vc,
                         const int* __restrict__ cnt)
{
    const int b = blockIdx.y;
    const int c = cnt[b];
    const int padded = (c + 63) & ~63;
    const int i = blockIdx.x * 256 + threadIdx.x;   // < 64*512
    {
        int r = i >> 9, col = i & 511;
        int rpos = c + r;
        if (rpos < padded)
            Kc[((size_t)b * SEQ + rpos) * DIMSZ + col] = 0.f;
    }
    {
        int d = i >> 6, k = i & 63;
        int cpos = c + k;
        if (cpos < padded)
            Vc[((size_t)b * DIMSZ + d) * SEQ + cpos] = 0.f;
    }
}

// ===========================================================================
// Prep: round x and the four W matrices to tf32 once (float4 grid-stride).
// ===========================================================================
#define XN4  (M_TOT * DIMSZ / 4)     // 1048576
#define WN4  (DIMSZ * DIMSZ / 4)     // 65536
#define PREP_TOT (XN4 + 4 * WN4)     // 1310720

__global__ void prep_tf32(const float* __restrict__ x,
                          const float* __restrict__ wq,
                          const float* __restrict__ wk,
                          const float* __restrict__ wv,
                          const float* __restrict__ wo,
                          float* __restrict__ gx, float* __restrict__ gw)
{
    int i = blockIdx.x * 256 + threadIdx.x;
    if (i >= PREP_TOT) return;
    const float4* src;
    float4* dst;
    int off;
    if (i < XN4) {
        src = (const float4*)x; dst = (float4*)gx; off = i;
    } else {
        int j = i - XN4;
        int which = j >> 16;          // j / WN4
        off = j & (WN4 - 1);
        const float* ws = (which == 0) ? wq : (which == 1) ? wk
                        : (which == 2) ? wv : wo;
        src = (const float4*)ws;
        dst = (float4*)(gw + (size_t)which * DIMSZ * DIMSZ);
    }
    float4 v = src[off];
    uint4 t = cvt4(v);
    dst[off] = *reinterpret_cast<float4*>(&t);
}

// ===========================================================================
// Shared GEMM mainloop (identical to R14):  128x128 CTA, 8 warps, cp.async.
// ===========================================================================
#define G2_STAGE 32768
#define G2_SMEM  (2 * G2_STAGE)

__device__ __forceinline__ void gemm_core(
    const float* __restrict__ A, const float* __restrict__ W,
    uint32_t sb, int rowBase, int colBase,
    int tid, int l, int wm, int wn, float acc[2][8][4])
{
    auto issue = [&](int c, int buf) {
        const uint32_t base = sb + buf * G2_STAGE;
#pragma unroll
        for (int i = 0; i < 4; i++) {
            int idx = tid + i * 256;
            int r = idx >> 3, cc = idx & 7;
            cpa16(base + r * 128 + ((cc ^ (r & 7)) << 4),
                  A + (size_t)(rowBase + r) * DIMSZ + c * 32 + cc * 4);
        }
#pragma unroll
        for (int i = 0; i < 4; i++) {
            int idx = tid + i * 256;
            int r = idx >> 3, cc = idx & 7;
            cpa16(base + 16384 + r * 128 + ((cc ^ (r & 7)) << 4),
                  W + (size_t)(colBase + r) * DIMSZ + c * 32 + cc * 4);
        }
    };

    issue(0, 0); CP_COMMIT();
    issue(1, 1); CP_COMMIT();

    for (int c = 0; c < 16; ++c) {
        const int buf = c & 1;
        CP_WAIT1();
        __syncthreads();
        const uint32_t ab = sb + buf * G2_STAGE;
        const uint32_t wb = ab + 16384;
#pragma unroll
        for (int s = 0; s < 4; ++s) {
            uint32_t a[2][4];
            const int ra  = 32 * wm + (l & 7) + (((l >> 3) & 1) << 3);
            const int cca = (2 * s + (l >> 4)) ^ (ra & 7);
            ldsm4(a[0][0], a[0][1], a[0][2], a[0][3],
                  ab + ra * 128 + (cca << 4));
            ldsm4(a[1][0], a[1][1], a[1][2], a[1][3],
                  ab + (ra + 16) * 128 + (cca << 4));
            uint32_t b[8][2];
#pragma unroll
            for (int p = 0; p < 4; p++) {
                int r  = 64 * wn + 16 * p + (l & 7) + ((l >> 4) << 3);
                int cc = (2 * s + ((l >> 3) & 1)) ^ (r & 7);
                ldsm4(b[2*p][0], b[2*p][1], b[2*p+1][0], b[2*p+1][1],
                      wb + r * 128 + (cc << 4));
            }
#pragma unroll
            for (int j = 0; j < 8; j++) {
                mma_tf32(acc[0][j], a[0], b[j][0], b[j][1]);
                mma_tf32(acc[1][j], a[1], b[j][0], b[j][1]);
            }
        }
        __syncthreads();
        if (c + 2 < 16) issue(c + 2, buf);
        CP_COMMIT();
    }
}

// Merged Q/K/V projection GEMM. z selects epilogue:
//   z=0: Q = tf32(acc * 0.125)                       (all tokens)
//   z=1: K = tf32(acc), stored at COMPACTED row j    (masked rows dropped)
//   z=2: V = tf32(acc), transposed to [b][dim][j]    (masked cols dropped)
__global__ __launch_bounds__(256, 2)
void proj_gemm(const float* __restrict__ X, const float* __restrict__ Wall,
               float* __restrict__ Qd, float* __restrict__ Kd,
               float* __restrict__ Vd, const int* __restrict__ r2c)
{
    extern __shared__ char sm[];
    const uint32_t sb = smem_u32(sm);
    const int tid = threadIdx.x, l = tid & 31, wid = tid >> 5;
    const int wm = wid & 3, wn = wid >> 2;
    const int rowBase = blockIdx.y * 128, colBase = blockIdx.x * 128;
    const int z = blockIdx.z;
    const float* W = Wall + (size_t)z * DIMSZ * DIMSZ;

    float acc[2][8][4];
#pragma unroll
    for (int at = 0; at < 2; at++)
#pragma unroll
        for (int j = 0; j < 8; j++)
#pragma unroll
            for (int q = 0; q < 4; q++) acc[at][j][q] = 0.f;

    gemm_core(X, W, sb, rowBase, colBase, tid, l, wm, wn, acc);

#pragma unroll
    for (int at = 0; at < 2; at++) {
        int r0 = rowBase + 32 * wm + 16 * at + (l >> 2);
#pragma unroll
        for (int half = 0; half < 2; half++) {
            int r = r0 + 8 * half;
            int bb  = r >> 11;
            int tok = r & (SEQ - 1);
            int j2c = (z == 0) ? 0 : __ldg(&r2c[bb * SEQ + tok]);
#pragma unroll
            for (int j = 0; j < 8; j++) {
                int col = colBase + 64 * wn + 8 * j + 2 * (l & 3);
                float v0 = acc[at][j][2 * half];
                float v1 = acc[at][j][2 * half + 1];
                if (z == 0) {
                    *(float2*)&Qd[(size_t)r * DIMSZ + col] =
                        make_float2(__uint_as_float(f2tf(v0 * 0.125f)),
                                    __uint_as_float(f2tf(v1 * 0.125f)));
                } else if (z == 1) {
                    if (j2c >= 0)
                        *(float2*)&Kd[((size_t)(bb * SEQ + j2c)) * DIMSZ + col] =
                            make_float2(__uint_as_float(f2tf(v0)),
                                        __uint_as_float(f2tf(v1)));
                } else {
                    if (j2c >= 0) {
                        Vd[((size_t)(bb * DIMSZ + col))     * SEQ + j2c] =
                            __uint_as_float(f2tf(v0));
                        Vd[((size_t)(bb * DIMSZ + col + 1)) * SEQ + j2c] =
                            __uint_as_float(f2tf(v1));
                    }
                }
            }
        }
    }
}

// Output GEMM: out = g_A (tf32 bits) * Wo^T, plain fp32 store.
__global__ __launch_bounds__(256, 2)
void gemm_out(const float* __restrict__ A, const float* __restrict__ W,
              float* __restrict__ D)
{
    extern __shared__ char sm[];
    const uint32_t sb = smem_u32(sm);
    const int tid = threadIdx.x, l = tid & 31, wid = tid >> 5;
    const int wm = wid & 3, wn = wid >> 2;
    const int rowBase = blockIdx.y * 128, colBase = blockIdx.x * 128;

    float acc[2][8][4];
#pragma unroll
    for (int at = 0; at < 2; at++)
#pragma unroll
        for (int j = 0; j < 8; j++)
#pragma unroll
            for (int q = 0; q < 4; q++) acc[at][j][q] = 0.f;

    gemm_core(A, W, sb, rowBase, colBase, tid, l, wm, wn, acc);

#pragma unroll
    for (int at = 0; at < 2; at++) {
        int r0 = rowBase + 32 * wm + 16 * at + (l >> 2);
#pragma unroll
        for (int j = 0; j < 8; j++) {
            int col = colBase + 64 * wn + 8 * j + 2 * (l & 3);
            *(float2*)&D[(size_t)r0 * DIMSZ + col] =
                make_float2(acc[at][j][0], acc[at][j][1]);
            *(float2*)&D[(size_t)(r0 + 8) * DIMSZ + col] =
                make_float2(acc[at][j][2], acc[at][j][3]);
        }
    }
}

// ===========================================================================
// Fused flash-attention over COMPACTED keys: loop runs ceil(cnt/64) tiles
// (~half of 32). Pad keys are suppressed with a register compare -> NEGV,
// exactly reproducing the reference's masked-score semantics (exp -> 0.0).
// ===========================================================================
#define AT_QS   0
#define AT_KS   32768
#define AT_VT   65536
#define AT_SMEM 98304

__global__ __launch_bounds__(128, 2)
void attn_tc(const float* __restrict__ Q, const float* __restrict__ K,
             const float* __restrict__ V, const int* __restrict__ cnt,
             float* __restrict__ Aout)
{
    extern __shared__ char sm[];
    const uint32_t sb = smem_u32(sm);
    const int tid = threadIdx.x;
    const int l   = tid & 31;
    const int w   = tid >> 5;
    const int b   = blockIdx.z;
    const int h   = blockIdx.y;
    const int qb  = blockIdx.x * 128;

    const float* Qb  = Q + ((size_t)b * SEQ) * DIMSZ + h * HD;
    const float* Kb  = K + ((size_t)b * SEQ) * DIMSZ + h * HD;   // compacted rows
    const float* Vtg = V + ((size_t)(b * DIMSZ + h * HD)) * SEQ; // compacted cols
    const int cntb  = __ldg(&cnt[b]);
    const int tiles = (cntb + 63) >> 6;

#pragma unroll
    for (int i = 0; i < 16; i++) {
        int idx = tid + i * 128;
        int r = idx >> 4, cc = idx & 15;
        cpa16(sb + AT_QS + r * 256 + ((cc ^ (r & 7)) << 4),
              Qb + (size_t)(qb + r) * DIMSZ + cc * 4);
    }

    auto issue_tile = [&](int t, int buf) {
        const int k0 = t * 64;
#pragma unroll
        for (int i = 0; i < 8; i++) {
            int idx = tid + i * 128;
            int key = idx >> 4, cc = idx & 15;
            cpa16(sb + AT_KS + buf * 16384 + key * 256 + ((cc ^ (key & 7)) << 4),
                  Kb + (size_t)(k0 + key) * DIMSZ + cc * 4);
        }
#pragma unroll
        for (int i = 0; i < 8; i++) {
            int idx = tid + i * 128;
            int d = idx >> 4, cc = idx & 15;
            cpa16(sb + AT_VT + buf * 16384 + d * 256 + ((cc ^ (d & 7)) << 4),
                  Vtg + (size_t)d * SEQ + k0 + cc * 4);
        }
    };

    issue_tile(0, 0); CP_COMMIT();
    issue_tile(1, 1); CP_COMMIT();

    float O[2][8][4];
    float mr[4], ls[4];
#pragma unroll
    for (int i = 0; i < 4; i++) { mr[i] = -1e30f; ls[i] = 0.f; }
#pragma unroll
    for (int at = 0; at < 2; at++)
#pragma unroll
        for (int j = 0; j < 8; j++)
#pragma unroll
            for (int q = 0; q < 4; q++) O[at][j][q] = 0.f;

    const int src0 = (l & ~3) | ((l & 3) >> 1);
    const int src1 = src0 + 2;
    const bool oddc = (l & 1);
    const int kAc = 2 * (l & 3);

    for (int t = 0; t < tiles; t++) {
        const int buf = t & 1;
        CP_WAIT1();
        __syncthreads();
        const uint32_t ksb = sb + AT_KS + buf * 16384;
        const uint32_t vtb = sb + AT_VT + buf * 16384;

        float S[2][8][4];
#pragma unroll
        for (int at = 0; at < 2; at++)
#pragma unroll
            for (int j = 0; j < 8; j++)
#pragma unroll
                for (int q = 0; q < 4; q++) S[at][j][q] = 0.f;

#pragma unroll
        for (int s = 0; s < 8; ++s) {
            uint32_t a0[4], a1[4];
            const int ra  = 32 * w + (l & 7) + (((l >> 3) & 1) << 3);
            const int cca = (2 * s + (l >> 4)) ^ (ra & 7);
            ldsm4(a0[0], a0[1], a0[2], a0[3],
                  sb + AT_QS + ra * 256 + (cca << 4));
            ldsm4(a1[0], a1[1], a1[2], a1[3],
                  sb + AT_QS + (ra + 16) * 256 + (cca << 4));
            uint32_t bq[8][2];
#pragma unroll
            for (int p = 0; p < 4; p++) {
                int r  = 16 * p + (l & 7) + ((l >> 4) << 3);
                int cc = (2 * s + ((l >> 3) & 1)) ^ (r & 7);
                ldsm4(bq[2*p][0], bq[2*p][1], bq[2*p+1][0], bq[2*p+1][1],
                      ksb + r * 256 + (cc << 4));
            }
#pragma unroll
            for (int j = 0; j < 8; j++) {
                mma_tf32(S[0][j], a0, bq[j][0], bq[j][1]);
                mma_tf32(S[1][j], a1, bq[j][0], bq[j][1]);
            }
        }

        // suppress pad keys (key index >= cnt) -> NEGV, as reference masks
#pragma unroll
        for (int j = 0; j < 8; j++) {
            int k0i = (t << 6) + 8 * j + kAc;
            bool v0 = k0i < cntb;
            bool v1 = (k0i + 1) < cntb;
#pragma unroll
            for (int at = 0; at < 2; at++) {
                S[at][j][0] = v0 ? S[at][j][0] : NEGV;
                S[at][j][1] = v1 ? S[at][j][1] : NEGV;
                S[at][j][2] = v0 ? S[at][j][2] : NEGV;
                S[at][j][3] = v1 ? S[at][j][3] : NEGV;
            }
        }

#pragma unroll
        for (int at = 0; at < 2; at++) {
            float mx0 = -1e30f, mx1 = -1e30f;
#pragma unroll
            for (int j = 0; j < 8; j++) {
                mx0 = fmaxf(mx0, fmaxf(S[at][j][0], S[at][j][1]));
                mx1 = fmaxf(mx1, fmaxf(S[at][j][2], S[at][j][3]));
            }
            mx0 = fmaxf(mx0, __shfl_xor_sync(0xffffffffu, mx0, 1));
            mx0 = fmaxf(mx0, __shfl_xor_sync(0xffffffffu, mx0, 2));
            mx1 = fmaxf(mx1, __shfl_xor_sync(0xffffffffu, mx1, 1));
            mx1 = fmaxf(mx1, __shfl_xor_sync(0xffffffffu, mx1, 2));

            float mn0 = fmaxf(mr[2*at],     mx0);
            float mn1 = fmaxf(mr[2*at + 1], mx1);
            float cr0 = __expf(mr[2*at]     - mn0);
            float cr1 = __expf(mr[2*at + 1] - mn1);
            mr[2*at] = mn0; mr[2*at + 1] = mn1;

            float rs0 = 0.f, rs1 = 0.f;
#pragma unroll
            for (int j = 0; j < 8; j++) {
                float p0 = __expf(S[at][j][0] - mn0);
                float p1 = __expf(S[at][j][1] - mn0);
                float p2 = __expf(S[at][j][2] - mn1);
                float p3 = __expf(S[at][j][3] - mn1);
                rs0 += p0 + p1; rs1 += p2 + p3;
                S[at][j][0] = p0; S[at][j][1] = p1;
                S[at][j][2] = p2; S[at][j][3] = p3;
            }
            rs0 += __shfl_xor_sync(0xffffffffu, rs0, 1);
            rs0 += __shfl_xor_sync(0xffffffffu, rs0, 2);
            rs1 += __shfl_xor_sync(0xffffffffu, rs1, 1);
            rs1 += __shfl_xor_sync(0xffffffffu, rs1, 2);
            ls[2*at]     = ls[2*at]     * cr0 + rs0;
            ls[2*at + 1] = ls[2*at + 1] * cr1 + rs1;

#pragma unroll
            for (int j = 0; j < 8; j++) {
                O[at][j][0] *= cr0; O[at][j][1] *= cr0;
                O[at][j][2] *= cr1; O[at][j][3] *= cr1;
            }
        }

#pragma unroll
        for (int s = 0; s < 8; ++s) {
            uint32_t af[2][4];
#pragma unroll
            for (int at = 0; at < 2; at++) {
                float p0 = S[at][s][0], p1 = S[at][s][1];
                float p2 = S[at][s][2], p3 = S[at][s][3];
                float e00 = __shfl_sync(0xffffffffu, p0, src0);
                float e01 = __shfl_sync(0xffffffffu, p1, src0);
                float e10 = __shfl_sync(0xffffffffu, p0, src1);
                float e11 = __shfl_sync(0xffffffffu, p1, src1);
                float f00 = __shfl_sync(0xffffffffu, p2, src0);
                float f01 = __shfl_sync(0xffffffffu, p3, src0);
                float f10 = __shfl_sync(0xffffffffu, p2, src1);
                float f11 = __shfl_sync(0xffffffffu, p3, src1);
                af[at][0] = f2tf(oddc ? e01 : e00);
                af[at][2] = f2tf(oddc ? e11 : e10);
                af[at][1] = f2tf(oddc ? f01 : f00);
                af[at][3] = f2tf(oddc ? f11 : f10);
            }
            uint32_t bv[8][2];
#pragma unroll
            for (int p = 0; p < 4; p++) {
                int r  = 16 * p + (l & 7) + ((l >> 4) << 3);
                int cc = (2 * s + ((l >> 3) & 1)) ^ (r & 7);
                ldsm4(bv[2*p][0], bv[2*p][1], bv[2*p+1][0], bv[2*p+1][1],
                      vtb + r * 256 + (cc << 4));
            }
#pragma unroll
            for (int j = 0; j < 8; j++) {
                mma_tf32(O[0][j], af[0], bv[j][0], bv[j][1]);
                mma_tf32(O[1][j], af[1], bv[j][0], bv[j][1]);
            }
        }

        __syncthreads();
        if (t + 2 < tiles) issue_tile(t + 2, buf);
        CP_COMMIT();
    }

    // epilogue: normalize, tf32-round (feeds gemm_out raw-copy staging)
#pragma unroll
    for (int at = 0; at < 2; at++) {
        const float inv0 = 1.0f / ls[2*at];
        const float inv1 = 1.0f / ls[2*at + 1];
        const int qr = qb + 32 * w + 16 * at + (l >> 2);
#pragma unroll
        for (int j = 0; j < 8; j++) {
            int col = h * HD + 8 * j + 2 * (l & 3);
            *(float2*)&Aout[((size_t)b * SEQ + qr) * DIMSZ + col] =
                make_float2(__uint_as_float(f2tf(O[at][j][0] * inv0)),
                            __uint_as_float(f2tf(O[at][j][1] * inv0)));
            *(float2*)&Aout[((size_t)b * SEQ + qr + 8) * DIMSZ + col] =
                make_float2(__uint_as_float(f2tf(O[at][j][2] * inv1)),
                            __uint_as_float(f2tf(O[at][j][3] * inv1)));
        }
    }
}

// ---------------------------------------------------------------------------
extern "C" void kernel_launch(void* const* d_in, const int* in_sizes, int n_in,
                              void* d_out, int out_size)
{
    (void)in_sizes; (void)n_in; (void)out_size;
    const float* x    = (const float*)d_in[0];
    const float* Wq   = (const float*)d_in[1];
    const float* Wk   = (const float*)d_in[2];
    const float* Wv   = (const float*)d_in[3];
    const float* Wo   = (const float*)d_in[4];
    const int*   mask = (const int*)d_in[5];
    float*       out  = (float*)d_out;

    float *Qp, *Kp, *Vp, *Ap, *Xp, *Wp;
    int *r2cP, *cntP;
    cudaGetSymbolAddress((void**)&Qp, g_Q);
    cudaGetSymbolAddress((void**)&Kp, g_K);
    cudaGetSymbolAddress((void**)&Vp, g_V);
    cudaGetSymbolAddress((void**)&Ap, g_A);
    cudaGetSymbolAddress((void**)&Xp, g_X);
    cudaGetSymbolAddress((void**)&Wp, g_W);
    cudaGetSymbolAddress((void**)&r2cP, g_r2c);
    cudaGetSymbolAddress((void**)&cntP, g_cnt);

    cudaFuncSetAttribute(proj_gemm,
                         cudaFuncAttributeMaxDynamicSharedMemorySize, G2_SMEM);
    cudaFuncSetAttribute(gemm_out,
                         cudaFuncAttributeMaxDynamicSharedMemorySize, G2_SMEM);
    cudaFuncSetAttribute(attn_tc,
                         cudaFuncAttributeMaxDynamicSharedMemorySize, AT_SMEM);

    mask_scan<<<BSZ, 256>>>(mask, r2cP, cntP);
    prep_tf32<<<(PREP_TOT + 255) / 256, 256>>>(x, Wq, Wk, Wv, Wo, Xp, Wp);
    zero_pad<<<dim3(128, BSZ), 256>>>(Kp, Vp, cntP);

    proj_gemm<<<dim3(DIMSZ / 128, M_TOT / 128, 3), 256, G2_SMEM>>>(
        Xp, Wp, Qp, Kp, Vp, r2cP);

    attn_tc<<<dim3(SEQ / 128, HEADS, BSZ), 128, AT_SMEM>>>(Qp, Kp, Vp, cntP, Ap);

    gemm_out<<<dim3(DIMSZ / 128, M_TOT / 128), 256, G2_SMEM>>>(
        Ap, Wp + (size_t)3 * DIMSZ * DIMSZ, out);
}